// round 8
// baseline (speedup 1.0000x reference)
#include <cuda_runtime.h>

// ---------------------------------------------------------------------------
// RVQ, 8 layers. R6 (resubmit after infra fail): 8x8 thread tile (64 acc regs)
//  -> 2 CTAs/SM, 4 warps/SMSP. MTILE=64, JTILE=256, 256 thr/CTA, grid 1024.
//  LSU and FMA both ~saturated per the phase-accurate LDS cost model.
// ---------------------------------------------------------------------------

namespace {
constexpr int Bb    = 16;
constexpr int Dd    = 256;
constexpr int Tt    = 4096;
constexpr int NQ    = 8;
constexpr int NBINS = 1024;
constexpr int NVEC  = Bb * Tt;        // 65536
constexpr int MTILE = 64;
constexpr int JTILE = 256;
constexpr int GRID_L = NVEC / MTILE;  // 1024
constexpr int NTH   = 256;

constexpr int AS_STRIDE = 68;                   // A tile [k=256][m=64], 16B-aligned rows
constexpr int AS_FLOATS = 256 * AS_STRIDE;      // 17408
constexpr int CHUNK     = 16;
constexpr int BS_ROW    = 260;                  // 256 j + pad
constexpr int BS_BUF    = CHUNK * BS_ROW;       // 4160
constexpr int BS_FLOATS = 2 * BS_BUF;           // 8320
constexpr int SIDX_OFF  = AS_FLOATS + BS_FLOATS;// 25728
constexpr int WLOSS_OFF = SIDX_OFF + 64;
constexpr int SMEM_FLOATS = WLOSS_OFF + 16;
constexpr size_t SMEM_BYTES = (size_t)SMEM_FLOATS * sizeof(float);  // ~100.8 KB
}

// ---------------- device scratch --------------------------------------------
__device__ __align__(16) float g_resid[(size_t)NVEC * Dd];
__device__ __align__(16) float g_rr[NVEC];
__device__ __align__(16) float g_cc[NQ * NBINS];
__device__ __align__(16) float g_losspart[NQ * GRID_L];

// ---------------- packed f32x2 helpers --------------------------------------
__device__ __forceinline__ unsigned long long dup2(float a) {
    unsigned long long r;
    asm("mov.b64 %0, {%1, %1};" : "=l"(r) : "f"(a));
    return r;
}
__device__ __forceinline__ float2 unpack2(unsigned long long v) {
    float2 r;
    asm("mov.b64 {%0, %1}, %2;" : "=f"(r.x), "=f"(r.y) : "l"(v));
    return r;
}
__device__ __forceinline__ void fma2(unsigned long long& d,
                                     unsigned long long a,
                                     unsigned long long b) {
    asm("fma.rn.f32x2 %0, %1, %2, %0;" : "+l"(d) : "l"(a), "l"(b));
}
__device__ __forceinline__ unsigned long long fma2v(unsigned long long a,
                                                    unsigned long long b,
                                                    unsigned long long c) {
    unsigned long long d;
    asm("fma.rn.f32x2 %0, %1, %2, %3;" : "=l"(d) : "l"(a), "l"(b), "l"(c));
    return d;
}
__device__ __forceinline__ unsigned long long add2(unsigned long long a,
                                                   unsigned long long b) {
    unsigned long long d;
    asm("add.rn.f32x2 %0, %1, %2;" : "=l"(d) : "l"(a), "l"(b));
    return d;
}

// ---------------- kernel: transpose x[B,D,T] -> resid[n][d] -----------------
__global__ void transpose_in_kernel(const float* __restrict__ x) {
    __shared__ float tile[32][33];
    const int b  = blockIdx.z;
    const int d0 = blockIdx.y * 32;
    const int t0 = blockIdx.x * 32;
    const int tx = threadIdx.x, ty = threadIdx.y;
    const float* xb = x + (size_t)b * Dd * Tt;
#pragma unroll
    for (int i = 0; i < 32; i += 8)
        tile[ty + i][tx] = xb[(size_t)(d0 + ty + i) * Tt + t0 + tx];
    __syncthreads();
#pragma unroll
    for (int i = 0; i < 32; i += 8) {
        const int t = t0 + ty + i;
        g_resid[(size_t)(b * Tt + t) * Dd + d0 + tx] = tile[tx][ty + i];
    }
}

// ---------------- kernel: row squared norms ---------------------------------
__global__ void rownorm_kernel() {
    const int row  = blockIdx.x * 8 + (threadIdx.x >> 5);
    const int lane = threadIdx.x & 31;
    const float* r = g_resid + (size_t)row * Dd;
    float s = 0.f;
#pragma unroll
    for (int i = 0; i < 8; i++) { float v = r[i * 32 + lane]; s = fmaf(v, v, s); }
#pragma unroll
    for (int o = 16; o; o >>= 1) s += __shfl_down_sync(0xffffffffu, s, o);
    if (!lane) g_rr[row] = s;
}

// ---------------- kernel: codebook squared norms ----------------------------
__global__ void codenorm_kernel(const float* __restrict__ cbs) {
    const int c    = blockIdx.x * 8 + (threadIdx.x >> 5);
    const int lane = threadIdx.x & 31;
    const float* r = cbs + (size_t)c * Dd;
    float s = 0.f;
#pragma unroll
    for (int i = 0; i < 8; i++) { float v = r[i * 32 + lane]; s = fmaf(v, v, s); }
#pragma unroll
    for (int o = 16; o; o >>= 1) s += __shfl_down_sync(0xffffffffu, s, o);
    if (!lane) g_cc[c] = s;
}

// ---------------- kernel: one RVQ layer -------------------------------------
__global__ __launch_bounds__(NTH, 2)
void rvq_layer_kernel(const float* __restrict__ cb,
                      int layer,
                      float* __restrict__ codes_out)
{
    extern __shared__ float sm[];
    float* As    = sm;                       // [256][68]
    float* Bs    = sm + AS_FLOATS;           // 2 x [16][260]
    int*   sidx  = (int*)(sm + SIDX_OFF);    // [64]
    float* wloss = sm + WLOSS_OFF;           // [8]

    const int tid  = threadIdx.x;
    const int tm   = tid >> 5;     // 0..7 : 8 m rows each (= warp id)
    const int tj   = tid & 31;     // 0..31: 8 j each (4 + 4 split)
    const int n0   = blockIdx.x * MTILE;
    const float* ccL = g_cc + layer * NBINS;

    // ---- A tile: As[d][m] = resid[(n0+m)*256 + d] ----
    {
        const float* rp = g_resid + (size_t)n0 * Dd + tid;
        float* ap = As + tid * AS_STRIDE;
#pragma unroll 8
        for (int m = 0; m < MTILE; m++) ap[m] = rp[(size_t)m * Dd];
    }

    float best[8];
    int   bestj[8];
#pragma unroll
    for (int i = 0; i < 8; i++) { best[i] = 3.402823466e38f; bestj[i] = 0; }

    const unsigned long long NEG2 = dup2(-2.0f);
    __syncthreads();

    // ---- 4 j-tiles of 256 codes ----
#pragma unroll 1
    for (int jt = 0; jt < 4; jt++) {
        const int j0 = jt * JTILE;
        const float* cbp = cb + (size_t)(j0 + tid) * Dd;

        unsigned long long acc[4][8];
#pragma unroll
        for (int mp = 0; mp < 4; mp++)
#pragma unroll
            for (int p = 0; p < 8; p++) acc[mp][p] = 0ull;

        // prologue: chunk 0 -> buffer 0
        float4 v0 = *(const float4*)(cbp);
        float4 v1 = *(const float4*)(cbp + 4);
        float4 v2 = *(const float4*)(cbp + 8);
        float4 v3 = *(const float4*)(cbp + 12);
        {
            float* dst = Bs + tid;
            dst[0*BS_ROW]=v0.x; dst[1*BS_ROW]=v0.y; dst[2*BS_ROW]=v0.z; dst[3*BS_ROW]=v0.w;
            dst[4*BS_ROW]=v1.x; dst[5*BS_ROW]=v1.y; dst[6*BS_ROW]=v1.z; dst[7*BS_ROW]=v1.w;
            dst[8*BS_ROW]=v2.x; dst[9*BS_ROW]=v2.y; dst[10*BS_ROW]=v2.z; dst[11*BS_ROW]=v2.w;
            dst[12*BS_ROW]=v3.x; dst[13*BS_ROW]=v3.y; dst[14*BS_ROW]=v3.z; dst[15*BS_ROW]=v3.w;
        }
        __syncthreads();

#pragma unroll 1
        for (int c = 0; c < 16; c++) {
            if (c < 15) {
                const float* g = cbp + (c + 1) * CHUNK;
                v0 = *(const float4*)(g);
                v1 = *(const float4*)(g + 4);
                v2 = *(const float4*)(g + 8);
                v3 = *(const float4*)(g + 12);
            }
            const float* ab = As + (c * CHUNK) * AS_STRIDE + 8 * tm;
            const float* bb = Bs + (c & 1) * BS_BUF + 4 * tj;
#pragma unroll 8
            for (int kk = 0; kk < CHUNK; kk++) {
                const float* ar = ab + kk * AS_STRIDE;
                const ulonglong2 A0 = *(const ulonglong2*)(ar);
                const ulonglong2 A1 = *(const ulonglong2*)(ar + 4);
                const float* brr = bb + kk * BS_ROW;
                const float4 b0 = *(const float4*)(brr);
                const float4 b1 = *(const float4*)(brr + 128);
                unsigned long long bu[8];
                bu[0]=dup2(b0.x); bu[1]=dup2(b0.y); bu[2]=dup2(b0.z); bu[3]=dup2(b0.w);
                bu[4]=dup2(b1.x); bu[5]=dup2(b1.y); bu[6]=dup2(b1.z); bu[7]=dup2(b1.w);
#pragma unroll
                for (int p = 0; p < 8; p++) {
                    fma2(acc[0][p], A0.x, bu[p]);
                    fma2(acc[1][p], A0.y, bu[p]);
                    fma2(acc[2][p], A1.x, bu[p]);
                    fma2(acc[3][p], A1.y, bu[p]);
                }
            }
            if (c < 15) {
                float* dst = Bs + ((c + 1) & 1) * BS_BUF + tid;
                dst[0*BS_ROW]=v0.x; dst[1*BS_ROW]=v0.y; dst[2*BS_ROW]=v0.z; dst[3*BS_ROW]=v0.w;
                dst[4*BS_ROW]=v1.x; dst[5*BS_ROW]=v1.y; dst[6*BS_ROW]=v1.z; dst[7*BS_ROW]=v1.w;
                dst[8*BS_ROW]=v2.x; dst[9*BS_ROW]=v2.y; dst[10*BS_ROW]=v2.z; dst[11*BS_ROW]=v2.w;
                dst[12*BS_ROW]=v3.x; dst[13*BS_ROW]=v3.y; dst[14*BS_ROW]=v3.z; dst[15*BS_ROW]=v3.w;
            }
            __syncthreads();
        }

        // epilogue: distances + running argmin (in-thread j visits ascending)
        const float4 cc0 = *(const float4*)(ccL + j0 + 4 * tj);
        const float4 cc1 = *(const float4*)(ccL + j0 + 128 + 4 * tj);
        const float ccv[8] = {cc0.x, cc0.y, cc0.z, cc0.w, cc1.x, cc1.y, cc1.z, cc1.w};
        const ulonglong2 R0 = *(const ulonglong2*)(g_rr + n0 + 8 * tm);
        const ulonglong2 R1 = *(const ulonglong2*)(g_rr + n0 + 8 * tm + 4);
        const unsigned long long rrp[4] = {R0.x, R0.y, R1.x, R1.y};
#pragma unroll
        for (int p = 0; p < 8; p++) {
            const int j = j0 + 4 * tj + ((p < 4) ? p : (124 + p));
            const unsigned long long ccp2 = dup2(ccv[p]);
#pragma unroll
            for (int mp = 0; mp < 4; mp++) {
                // mirrors jax: fmaf(-2, dot, rr) + cc (packed, per-lane rounding)
                const unsigned long long d2 = add2(fma2v(acc[mp][p], NEG2, rrp[mp]), ccp2);
                const float2 dd = unpack2(d2);
                if (dd.x < best[2*mp])   { best[2*mp]   = dd.x; bestj[2*mp]   = j; }
                if (dd.y < best[2*mp+1]) { best[2*mp+1] = dd.y; bestj[2*mp+1] = j; }
            }
        }
    }

    // ---- warp-level argmin over the 32 tj lanes (warp owns rows 8*tm..+7) --
#pragma unroll
    for (int i = 0; i < 8; i++) {
        float bv = best[i];
        int   bj = bestj[i];
#pragma unroll
        for (int off = 16; off; off >>= 1) {
            const float ov = __shfl_xor_sync(0xffffffffu, bv, off);
            const int   oj = __shfl_xor_sync(0xffffffffu, bj, off);
            if (ov < bv || (ov == bv && oj < bj)) { bv = ov; bj = oj; }
        }
        if (tj == 0) sidx[8 * tm + i] = bj;
    }
    __syncthreads();

    // ---- fused update: resid -= cb[idx]; new norms; codes; loss ----
    const int wid = tid >> 5, lane = tid & 31;
    float wl = 0.f;
    for (int m = wid; m < MTILE; m += 8) {
        const int j = sidx[m];
        const float* q = cb + (size_t)j * Dd;
        float* rout = g_resid + (size_t)(n0 + m) * Dd;
        float s = 0.f;
#pragma unroll
        for (int i = 0; i < 8; i++) {
            const int d = i * 32 + lane;
            const float rn = As[d * AS_STRIDE + m] - q[d];
            rout[d] = rn;
            s = fmaf(rn, rn, s);
        }
#pragma unroll
        for (int o = 16; o; o >>= 1) s += __shfl_down_sync(0xffffffffu, s, o);
        if (!lane) {
            g_rr[n0 + m] = s;
            wl += s;
            if (codes_out) codes_out[(size_t)layer * NVEC + n0 + m] = (float)j;
        }
    }
    if (!lane) wloss[wid] = wl;
    __syncthreads();
    if (tid == 0) {
        float t = 0.f;
#pragma unroll
        for (int w = 0; w < 8; w++) t += wloss[w];
        g_losspart[layer * GRID_L + blockIdx.x] = t;
    }
}

// ---------------- kernel: quantized = x - resid_final, + loss ---------------
__global__ void finalize_kernel(const float* __restrict__ x,
                                float* __restrict__ out,
                                float* __restrict__ loss_dst) {
    __shared__ float tile[32][33];
    const int b  = blockIdx.z;
    const int d0 = blockIdx.y * 32;
    const int t0 = blockIdx.x * 32;
    const int tx = threadIdx.x, ty = threadIdx.y;
#pragma unroll
    for (int i = 0; i < 32; i += 8)
        tile[ty + i][tx] = g_resid[(size_t)(b * Tt + t0 + ty + i) * Dd + d0 + tx];
    __syncthreads();
#pragma unroll
    for (int i = 0; i < 32; i += 8) {
        const size_t idx = (size_t)b * Dd * Tt + (size_t)(d0 + ty + i) * Tt + t0 + tx;
        out[idx] = x[idx] - tile[tx][ty + i];
    }
    if (loss_dst && blockIdx.x == 0 && blockIdx.y == 0 && blockIdx.z == 0 && ty == 0) {
        double s = 0.0;
        for (int i = tx; i < NQ * GRID_L; i += 32) s += (double)g_losspart[i];
#pragma unroll
        for (int o = 16; o; o >>= 1) s += __shfl_down_sync(0xffffffffu, s, o);
        if (tx == 0)
            *loss_dst = (float)(s / ((double)NQ * (double)NVEC * (double)Dd));
    }
}

// ---------------- launch -----------------------------------------------------
extern "C" void kernel_launch(void* const* d_in, const int* in_sizes, int n_in,
                              void* d_out, int out_size) {
    const float* x   = (const float*)d_in[0];
    const float* cbs = (const float*)d_in[1];
    float* out = (float*)d_out;

    const long long QN = (long long)Bb * Dd * Tt;
    const long long CN = (long long)NQ * Bb * Tt;
    float* codes = ((long long)out_size >= QN + CN) ? out + QN : nullptr;
    float* lossp = ((long long)out_size >= QN + CN + 1) ? out + QN + CN : nullptr;

    cudaFuncSetAttribute(rvq_layer_kernel,
                         cudaFuncAttributeMaxDynamicSharedMemorySize,
                         (int)SMEM_BYTES);

    transpose_in_kernel<<<dim3(Tt / 32, Dd / 32, Bb), dim3(32, 8)>>>(x);
    rownorm_kernel<<<NVEC / 8, 256>>>();
    codenorm_kernel<<<NQ * NBINS / 8, 256>>>(cbs);
    for (int l = 0; l < NQ; l++) {
        rvq_layer_kernel<<<GRID_L, NTH, SMEM_BYTES>>>(
            cbs + (size_t)l * NBINS * Dd, l, codes);
    }
    finalize_kernel<<<dim3(Tt / 32, Dd / 32, Bb), dim3(32, 8)>>>(x, out, lossp);
}

// round 10
// speedup vs baseline: 1.1592x; 1.1592x over previous
#include <cuda_runtime.h>

// ---------------------------------------------------------------------------
// RVQ, 8 layers. R9 (= R8 fixed): tensor-core GEMM (mma.sync m16n8k8 tf32,
//  3xTF32 split) + approximate top-2 argmin + exact fp32 refine of the 2
//  candidates. Codebook hi/lo pre-split, fragment-ordered, in global scratch.
// ---------------------------------------------------------------------------

namespace {
constexpr int Bb    = 16;
constexpr int Dd    = 256;
constexpr int Tt    = 4096;
constexpr int NQ    = 8;
constexpr int NBINS = 1024;
constexpr int NVEC  = Bb * Tt;        // 65536
constexpr int MTILE = 128;
constexpr int GRID_L = NVEC / MTILE;  // 512
constexpr int NTH   = 256;

constexpr int AF4 = 8192;             // A frags: 8 mb x 32 c8 x 32 lanes (float4)
constexpr int BS4 = 2048;             // per buffer: 4 k8 x 2 h x 8 p x 32 lanes
constexpr int SMEM_BYTES_L = (AF4 + 2 * BS4) * 16   // 196608
                           + 128 * 4                // ccs
                           + 4 * 256 * 4            // s_v1,s_v2,s_j1,s_j2
                           + 128 * 8                // cand (int2)
                           + 128 * 4                // sidx
                           + 64;                    // wloss + pad  => 202816
}

// ---------------- device scratch --------------------------------------------
__device__ __align__(16) float  g_resid[(size_t)NVEC * Dd];     // 64 MB
__device__ __align__(16) float  g_rr[NVEC];
__device__ __align__(16) float  g_cc[NQ * NBINS];
__device__ __align__(16) float  g_losspart[NQ * GRID_L];
__device__ __align__(16) float4 g_cbfrag[1048576];              // 16 MB hi/lo frags

// ---------------- helpers ----------------------------------------------------
__device__ __forceinline__ unsigned f2tf(float x) {
    unsigned r;
    asm("cvt.rna.tf32.f32 %0, %1;" : "=r"(r) : "f"(x));
    return r;
}
__device__ __forceinline__ void mma_tf32(float* d,
                                         unsigned a0, unsigned a1, unsigned a2, unsigned a3,
                                         unsigned b0, unsigned b1) {
    asm volatile(
        "mma.sync.aligned.m16n8k8.row.col.f32.tf32.tf32.f32 "
        "{%0,%1,%2,%3},{%4,%5,%6,%7},{%8,%9},{%0,%1,%2,%3};"
        : "+f"(d[0]), "+f"(d[1]), "+f"(d[2]), "+f"(d[3])
        : "r"(a0), "r"(a1), "r"(a2), "r"(a3), "r"(b0), "r"(b1));
}

// ---------------- kernel: transpose x[B,D,T] -> resid[n][d] -----------------
__global__ void transpose_in_kernel(const float* __restrict__ x) {
    __shared__ float tile[32][33];
    const int b  = blockIdx.z;
    const int d0 = blockIdx.y * 32;
    const int t0 = blockIdx.x * 32;
    const int tx = threadIdx.x, ty = threadIdx.y;
    const float* xb = x + (size_t)b * Dd * Tt;
#pragma unroll
    for (int i = 0; i < 32; i += 8)
        tile[ty + i][tx] = xb[(size_t)(d0 + ty + i) * Tt + t0 + tx];
    __syncthreads();
#pragma unroll
    for (int i = 0; i < 32; i += 8) {
        const int t = t0 + ty + i;
        g_resid[(size_t)(b * Tt + t) * Dd + d0 + tx] = tile[tx][ty + i];
    }
}

// ---------------- kernel: row squared norms ---------------------------------
__global__ void rownorm_kernel() {
    const int row  = blockIdx.x * 8 + (threadIdx.x >> 5);
    const int lane = threadIdx.x & 31;
    const float* r = g_resid + (size_t)row * Dd;
    float s = 0.f;
#pragma unroll
    for (int i = 0; i < 8; i++) { float v = r[i * 32 + lane]; s = fmaf(v, v, s); }
#pragma unroll
    for (int o = 16; o; o >>= 1) s += __shfl_down_sync(0xffffffffu, s, o);
    if (!lane) g_rr[row] = s;
}

// ---------------- kernel: codebook squared norms ----------------------------
__global__ void codenorm_kernel(const float* __restrict__ cbs) {
    const int c    = blockIdx.x * 8 + (threadIdx.x >> 5);
    const int lane = threadIdx.x & 31;
    const float* r = cbs + (size_t)c * Dd;
    float s = 0.f;
#pragma unroll
    for (int i = 0; i < 8; i++) { float v = r[i * 32 + lane]; s = fmaf(v, v, s); }
#pragma unroll
    for (int o = 16; o; o >>= 1) s += __shfl_down_sync(0xffffffffu, s, o);
    if (!lane) g_cc[c] = s;
}

// ---------------- kernel: build fragment-ordered tf32 hi/lo codebook --------
// idx bits = layer(3) | jb(3) | c8(5) | h(1) | p(3) | lane(5)
// element e of float4: nt = 2p + (e>>1); b-reg = e&1.
//  B frag (col-major k8 x n8): breg0 -> k=lane&3, n=lane>>2 ; breg1 -> k+4.
__global__ void cbfrag_prep(const float* __restrict__ cbs) {
    const unsigned idx = blockIdx.x * 256 + threadIdx.x;   // 0 .. 1048575
    const int lane  = idx & 31;
    const int p     = (idx >> 5) & 7;
    const int h     = (idx >> 8) & 1;
    const int c8    = (idx >> 9) & 31;
    const int jb    = (idx >> 14) & 7;
    const int layer = (int)(idx >> 17);
    float4 o;
    float* oe = &o.x;
#pragma unroll
    for (int e = 0; e < 4; e++) {
        const int nt = 2 * p + (e >> 1);
        const int j  = jb * 128 + nt * 8 + (lane >> 2);
        const int k  = c8 * 8 + (lane & 3) + ((e & 1) ? 4 : 0);
        const float x = cbs[((size_t)layer * NBINS + j) * Dd + k];
        const unsigned hb = f2tf(x);
        oe[e] = (h == 0) ? __uint_as_float(hb)
                         : __uint_as_float(f2tf(x - __uint_as_float(hb)));
    }
    g_cbfrag[idx] = o;
}

// ---------------- top-2 insert ----------------------------------------------
__device__ __forceinline__ void top2_upd(float& v1, int& j1, float& v2, int& j2,
                                         float v, int j) {
    if (v < v1 || (v == v1 && j < j1)) { v2 = v1; j2 = j1; v1 = v; j1 = j; }
    else if (v < v2 || (v == v2 && j < j2)) { v2 = v; j2 = j; }
}

// ---------------- kernel: one RVQ layer (tensor-core) ------------------------
__global__ __launch_bounds__(NTH, 1)
void rvq_layer_kernel(const float* __restrict__ cb,   // layer codebook [1024][256]
                      int layer,
                      float* __restrict__ codes_out)
{
    extern __shared__ float4 sm4[];
    float4* Af4 = sm4;                 // [8 mb][32 c8][32 lane]
    float4* Bs4 = sm4 + AF4;           // [2 buf][4 k8][2 h][8 p][32 lane]
    float*  ccs   = (float*)(sm4 + AF4 + 2 * BS4);       // [128]
    float*  s_v1  = ccs + 128;                           // [2][128]
    float*  s_v2  = s_v1 + 256;                          // [2][128]
    int*    s_j1  = (int*)(s_v2 + 256);                  // [2][128]
    int*    s_j2  = s_j1 + 256;                          // [2][128]
    int2*   cand  = (int2*)(s_j2 + 256);                 // [128]
    int*    sidx  = (int*)(cand + 128);                  // [128]
    float*  wloss = (float*)(sidx + 128);                // [8]

    const int tid  = threadIdx.x;
    const int wid  = tid >> 5;
    const int lane = tid & 31;
    const int ms   = wid & 3;    // m-strip (32 rows each)
    const int jh   = wid >> 2;   // j-half within a 128-j tile
    const int n0   = blockIdx.x * MTILE;
    const float* ccL = g_cc + layer * NBINS;

    // ---- A fragment load: Af4[(mb*32 + c8)*32 + lane] ----
    for (int pr = wid * 32; pr < wid * 32 + 32; pr++) {
        const int mb = pr >> 5, c8 = pr & 31;
        const float* r0 = g_resid + (size_t)(n0 + mb * 16 + (lane >> 2)) * Dd
                         + c8 * 8 + (lane & 3);
        const float* r1 = r0 + 8 * Dd;
        Af4[pr * 32 + lane] = make_float4(r0[0], r1[0], r0[4], r1[4]);
    }

    float bestv1[4], bestv2[4];
    int   bjj1[4], bjj2[4];
#pragma unroll
    for (int s = 0; s < 4; s++) {
        bestv1[s] = bestv2[s] = 3.402823466e38f;
        bjj1[s] = bjj2[s] = 0x7fffffff;
    }
    __syncthreads();

    // ---- 8 j-tiles of 128 codes ----
#pragma unroll 1
    for (int jt = 0; jt < 8; jt++) {
        const int j0 = jt * 128;
        const unsigned gbase = ((unsigned)layer * 8 + jt) * 16384u;

        float acc[2][8][4];
#pragma unroll
        for (int mt = 0; mt < 2; mt++)
#pragma unroll
            for (int nt = 0; nt < 8; nt++)
#pragma unroll
                for (int c = 0; c < 4; c++) acc[mt][nt][c] = 0.f;

        if (tid < 128) ccs[tid] = ccL[j0 + tid];

        // prologue: chunk 0 (c8 0..3) -> buffer 0
#pragma unroll
        for (int i = 0; i < 8; i++)
            Bs4[i * 256 + tid] = g_cbfrag[gbase + i * 256 + tid];
        __syncthreads();

#pragma unroll 1
        for (int ch = 0; ch < 8; ch++) {
            float4 pf[8];
            if (ch < 7) {
                const unsigned src = gbase + (unsigned)(ch + 1) * 2048u;
#pragma unroll
                for (int i = 0; i < 8; i++) pf[i] = g_cbfrag[src + i * 256 + tid];
            }
            const float4* bbuf = Bs4 + (ch & 1) * BS4;
#pragma unroll
            for (int k8 = 0; k8 < 4; k8++) {
                const int c8 = ch * 4 + k8;
                unsigned ahi[2][4], alo[2][4];
#pragma unroll
                for (int mt = 0; mt < 2; mt++) {
                    const float4 av = Af4[((ms * 2 + mt) * 32 + c8) * 32 + lane];
                    const float ae[4] = {av.x, av.y, av.z, av.w};
#pragma unroll
                    for (int e = 0; e < 4; e++) {
                        const unsigned hb = f2tf(ae[e]);
                        ahi[mt][e] = hb;
                        alo[mt][e] = f2tf(ae[e] - __uint_as_float(hb));
                    }
                }
#pragma unroll
                for (int p = 0; p < 4; p++) {
                    const uint4 bh = *(const uint4*)&bbuf[(k8 * 2 + 0) * 256 + (jh * 4 + p) * 32 + lane];
                    const uint4 bl = *(const uint4*)&bbuf[(k8 * 2 + 1) * 256 + (jh * 4 + p) * 32 + lane];
#pragma unroll
                    for (int mt = 0; mt < 2; mt++) {
                        float* aeven = acc[mt][2 * p];
                        float* aodd  = acc[mt][2 * p + 1];
                        mma_tf32(aeven, ahi[mt][0], ahi[mt][1], ahi[mt][2], ahi[mt][3], bh.x, bh.y);
                        mma_tf32(aeven, ahi[mt][0], ahi[mt][1], ahi[mt][2], ahi[mt][3], bl.x, bl.y);
                        mma_tf32(aeven, alo[mt][0], alo[mt][1], alo[mt][2], alo[mt][3], bh.x, bh.y);
                        mma_tf32(aodd,  ahi[mt][0], ahi[mt][1], ahi[mt][2], ahi[mt][3], bh.z, bh.w);
                        mma_tf32(aodd,  ahi[mt][0], ahi[mt][1], ahi[mt][2], ahi[mt][3], bl.z, bl.w);
                        mma_tf32(aodd,  alo[mt][0], alo[mt][1], alo[mt][2], alo[mt][3], bh.z, bh.w);
                    }
                }
            }
            if (ch < 7) {
                float4* dst = Bs4 + ((ch + 1) & 1) * BS4;
#pragma unroll
                for (int i = 0; i < 8; i++) dst[i * 256 + tid] = pf[i];
            }
            __syncthreads();
        }

        // epilogue: approx dists (rr omitted: row-constant, argmin-invariant),
        // maintain per-slot top-2.  D frag: c0->(row g, col 2t) c1->(g,2t+1)
        // c2->(g+8,2t) c3->(g+8,2t+1), g=lane>>2, t=lane&3.
#pragma unroll
        for (int mt = 0; mt < 2; mt++)
#pragma unroll
            for (int nt = 0; nt < 8; nt++) {
                const int jl = jh * 64 + nt * 8 + 2 * (lane & 3);
                const int j  = j0 + jl;
                const float d0 = fmaf(-2.f, acc[mt][nt][0], ccs[jl]);
                const float d1 = fmaf(-2.f, acc[mt][nt][1], ccs[jl + 1]);
                const float d2 = fmaf(-2.f, acc[mt][nt][2], ccs[jl]);
                const float d3 = fmaf(-2.f, acc[mt][nt][3], ccs[jl + 1]);
                const int s0 = mt * 2, s1 = mt * 2 + 1;
                top2_upd(bestv1[s0], bjj1[s0], bestv2[s0], bjj2[s0], d0, j);
                top2_upd(bestv1[s0], bjj1[s0], bestv2[s0], bjj2[s0], d1, j + 1);
                top2_upd(bestv1[s1], bjj1[s1], bestv2[s1], bjj2[s1], d2, j);
                top2_upd(bestv1[s1], bjj1[s1], bestv2[s1], bjj2[s1], d3, j + 1);
            }
        __syncthreads();   // ccs/Bs reuse across jt
    }

    // ---- merge top-2 across the 4 lanes sharing a row ----
#pragma unroll
    for (int s = 0; s < 4; s++) {
#pragma unroll
        for (int off = 1; off <= 2; off <<= 1) {
            const float ov1 = __shfl_xor_sync(0xffffffffu, bestv1[s], off);
            const int   oj1 = __shfl_xor_sync(0xffffffffu, bjj1[s], off);
            const float ov2 = __shfl_xor_sync(0xffffffffu, bestv2[s], off);
            const int   oj2 = __shfl_xor_sync(0xffffffffu, bjj2[s], off);
            top2_upd(bestv1[s], bjj1[s], bestv2[s], bjj2[s], ov1, oj1);
            top2_upd(bestv1[s], bjj1[s], bestv2[s], bjj2[s], ov2, oj2);
        }
        if ((lane & 3) == 0) {
            const int r = ms * 32 + (s >> 1) * 16 + (s & 1) * 8 + (lane >> 2);
            s_v1[jh * 128 + r] = bestv1[s]; s_j1[jh * 128 + r] = bjj1[s];
            s_v2[jh * 128 + r] = bestv2[s]; s_j2[jh * 128 + r] = bjj2[s];
        }
    }
    __syncthreads();

    // ---- merge the two j-halves per row -> 2 candidates ----
    if (tid < 128) {
        float v1 = s_v1[tid], v2 = s_v2[tid];
        int   j1 = s_j1[tid], j2 = s_j2[tid];
        top2_upd(v1, j1, v2, j2, s_v1[128 + tid], s_j1[128 + tid]);
        top2_upd(v1, j1, v2, j2, s_v2[128 + tid], s_j2[128 + tid]);
        cand[tid] = make_int2(j1, j2);
    }
    __syncthreads();

    // ---- exact fp32 refine of the 2 candidates (1 warp : 16 rows) ----
    for (int i = 0; i < 16; i++) {
        const int r = wid * 16 + i;
        const int j1 = cand[r].x, j2 = cand[r].y;
        const float* rv = g_resid + (size_t)(n0 + r) * Dd;
        const float* c1 = cb + (size_t)j1 * Dd;
        const float* c2 = cb + (size_t)j2 * Dd;
        float s1 = 0.f, s2 = 0.f;
#pragma unroll
        for (int kq = 0; kq < 8; kq++) {
            const float rvx = rv[kq * 32 + lane];
            s1 = fmaf(rvx, c1[kq * 32 + lane], s1);
            s2 = fmaf(rvx, c2[kq * 32 + lane], s2);
        }
#pragma unroll
        for (int o = 16; o; o >>= 1) {
            s1 += __shfl_down_sync(0xffffffffu, s1, o);
            s2 += __shfl_down_sync(0xffffffffu, s2, o);
        }
        if (!lane) {
            const float rrn = g_rr[n0 + r];
            const float d1 = fmaf(-2.f, s1, rrn) + ccL[j1];
            const float d2 = fmaf(-2.f, s2, rrn) + ccL[j2];
            sidx[r] = (d1 < d2 || (d1 == d2 && j1 < j2)) ? j1 : j2;
        }
    }
    __syncthreads();

    // ---- fused update: resid -= cb[idx]; new norms; codes; loss ----
    float wl = 0.f;
    for (int m = wid; m < MTILE; m += 8) {
        const int j = sidx[m];
        const float* q = cb + (size_t)j * Dd;
        float* rout = g_resid + (size_t)(n0 + m) * Dd;
        float s = 0.f;
#pragma unroll
        for (int i = 0; i < 8; i++) {
            const int d = i * 32 + lane;
            const float rn = rout[d] - q[d];
            rout[d] = rn;
            s = fmaf(rn, rn, s);
        }
#pragma unroll
        for (int o = 16; o; o >>= 1) s += __shfl_down_sync(0xffffffffu, s, o);
        if (!lane) {
            g_rr[n0 + m] = s;
            wl += s;
            if (codes_out) codes_out[(size_t)layer * NVEC + n0 + m] = (float)j;
        }
    }
    if (!lane) wloss[wid] = wl;
    __syncthreads();
    if (tid == 0) {
        float t = 0.f;
#pragma unroll
        for (int w = 0; w < 8; w++) t += wloss[w];
        g_losspart[layer * GRID_L + blockIdx.x] = t;
    }
}

// ---------------- kernel: quantized = x - resid_final, + loss ---------------
__global__ void finalize_kernel(const float* __restrict__ x,
                                float* __restrict__ out,
                                float* __restrict__ loss_dst) {
    __shared__ float tile[32][33];
    const int b  = blockIdx.z;
    const int d0 = blockIdx.y * 32;
    const int t0 = blockIdx.x * 32;
    const int tx = threadIdx.x, ty = threadIdx.y;
#pragma unroll
    for (int i = 0; i < 32; i += 8)
        tile[ty + i][tx] = g_resid[(size_t)(b * Tt + t0 + ty + i) * Dd + d0 + tx];
    __syncthreads();
#pragma unroll
    for (int i = 0; i < 32; i += 8) {
        const size_t idx = (size_t)b * Dd * Tt + (size_t)(d0 + ty + i) * Tt + t0 + tx;
        out[idx] = x[idx] - tile[tx][ty + i];
    }
    if (loss_dst && blockIdx.x == 0 && blockIdx.y == 0 && blockIdx.z == 0 && ty == 0) {
        double s = 0.0;
        for (int i = tx; i < NQ * GRID_L; i += 32) s += (double)g_losspart[i];
#pragma unroll
        for (int o = 16; o; o >>= 1) s += __shfl_down_sync(0xffffffffu, s, o);
        if (tx == 0)
            *loss_dst = (float)(s / ((double)NQ * (double)NVEC * (double)Dd));
    }
}

// ---------------- launch -----------------------------------------------------
extern "C" void kernel_launch(void* const* d_in, const int* in_sizes, int n_in,
                              void* d_out, int out_size) {
    const float* x   = (const float*)d_in[0];
    const float* cbs = (const float*)d_in[1];
    float* out = (float*)d_out;

    const long long QN = (long long)Bb * Dd * Tt;
    const long long CN = (long long)NQ * Bb * Tt;
    float* codes = ((long long)out_size >= QN + CN) ? out + QN : nullptr;
    float* lossp = ((long long)out_size >= QN + CN + 1) ? out + QN + CN : nullptr;

    cudaFuncSetAttribute(rvq_layer_kernel,
                         cudaFuncAttributeMaxDynamicSharedMemorySize,
                         SMEM_BYTES_L);

    transpose_in_kernel<<<dim3(Tt / 32, Dd / 32, Bb), dim3(32, 8)>>>(x);
    rownorm_kernel<<<NVEC / 8, 256>>>();
    codenorm_kernel<<<NQ * NBINS / 8, 256>>>(cbs);
    cbfrag_prep<<<4096, 256>>>(cbs);
    for (int l = 0; l < NQ; l++) {
        rvq_layer_kernel<<<GRID_L, NTH, SMEM_BYTES_L>>>(
            cbs + (size_t)l * NBINS * Dd, l, codes);
    }
    finalize_kernel<<<dim3(Tt / 32, Dd / 32, Bb), dim3(32, 8)>>>(x, out, lossp);
}

// round 11
// speedup vs baseline: 1.4625x; 1.2616x over previous
#include <cuda_runtime.h>

// ---------------------------------------------------------------------------
// RVQ, 8 layers. R10: single-pass tf32 mma (hi only; was 3xTF32) -> 3x fewer
//  mma instructions (the measured binder: legacy mma rt~16cyc/SMSP).
//  Top-4 approximate candidates per row + exact fp32 re-rank (reference math).
//  A pre-rounded to tf32 in smem (no CVT in mainloop); codebook hi-only frags.
// ---------------------------------------------------------------------------

namespace {
constexpr int Bb    = 16;
constexpr int Dd    = 256;
constexpr int Tt    = 4096;
constexpr int NQ    = 8;
constexpr int NBINS = 1024;
constexpr int NVEC  = Bb * Tt;        // 65536
constexpr int MTILE = 128;
constexpr int GRID_L = NVEC / MTILE;  // 512
constexpr int NTH   = 256;

constexpr int AF4 = 8192;             // A frags: 8 mb x 32 c8 x 32 lanes (float4)
constexpr int BS4 = 1024;             // per buffer: 4 c8 x 8 p x 32 lanes (hi only)
constexpr int SMEM_BYTES_L = (AF4 + 2 * BS4) * 16   // 163840
                           + 128 * 4                // ccs
                           + 1024 * 4               // s_v  [2][128][4]
                           + 1024 * 4               // s_j  [2][128][4]
                           + 512 * 4                // cand4 [128][4]
                           + 128 * 4                // sidx
                           + 64;                    // wloss + pad => 175200
}

// ---------------- device scratch --------------------------------------------
__device__ __align__(16) float  g_resid[(size_t)NVEC * Dd];     // 64 MB
__device__ __align__(16) float  g_rr[NVEC];
__device__ __align__(16) float  g_cc[NQ * NBINS];
__device__ __align__(16) float  g_losspart[NQ * GRID_L];
__device__ __align__(16) float4 g_cbfrag[524288];               // 8 MB hi frags

// ---------------- helpers ----------------------------------------------------
__device__ __forceinline__ unsigned f2tf(float x) {
    unsigned r;
    asm("cvt.rna.tf32.f32 %0, %1;" : "=r"(r) : "f"(x));
    return r;
}
__device__ __forceinline__ void mma_tf32(float* d,
                                         unsigned a0, unsigned a1, unsigned a2, unsigned a3,
                                         unsigned b0, unsigned b1) {
    asm volatile(
        "mma.sync.aligned.m16n8k8.row.col.f32.tf32.tf32.f32 "
        "{%0,%1,%2,%3},{%4,%5,%6,%7},{%8,%9},{%0,%1,%2,%3};"
        : "+f"(d[0]), "+f"(d[1]), "+f"(d[2]), "+f"(d[3])
        : "r"(a0), "r"(a1), "r"(a2), "r"(a3), "r"(b0), "r"(b1));
}

// ---------------- kernel: transpose x[B,D,T] -> resid[n][d] -----------------
__global__ void transpose_in_kernel(const float* __restrict__ x) {
    __shared__ float tile[32][33];
    const int b  = blockIdx.z;
    const int d0 = blockIdx.y * 32;
    const int t0 = blockIdx.x * 32;
    const int tx = threadIdx.x, ty = threadIdx.y;
    const float* xb = x + (size_t)b * Dd * Tt;
#pragma unroll
    for (int i = 0; i < 32; i += 8)
        tile[ty + i][tx] = xb[(size_t)(d0 + ty + i) * Tt + t0 + tx];
    __syncthreads();
#pragma unroll
    for (int i = 0; i < 32; i += 8) {
        const int t = t0 + ty + i;
        g_resid[(size_t)(b * Tt + t) * Dd + d0 + tx] = tile[tx][ty + i];
    }
}

// ---------------- kernel: row squared norms ---------------------------------
__global__ void rownorm_kernel() {
    const int row  = blockIdx.x * 8 + (threadIdx.x >> 5);
    const int lane = threadIdx.x & 31;
    const float* r = g_resid + (size_t)row * Dd;
    float s = 0.f;
#pragma unroll
    for (int i = 0; i < 8; i++) { float v = r[i * 32 + lane]; s = fmaf(v, v, s); }
#pragma unroll
    for (int o = 16; o; o >>= 1) s += __shfl_down_sync(0xffffffffu, s, o);
    if (!lane) g_rr[row] = s;
}

// ---------------- kernel: codebook squared norms ----------------------------
__global__ void codenorm_kernel(const float* __restrict__ cbs) {
    const int c    = blockIdx.x * 8 + (threadIdx.x >> 5);
    const int lane = threadIdx.x & 31;
    const float* r = cbs + (size_t)c * Dd;
    float s = 0.f;
#pragma unroll
    for (int i = 0; i < 8; i++) { float v = r[i * 32 + lane]; s = fmaf(v, v, s); }
#pragma unroll
    for (int o = 16; o; o >>= 1) s += __shfl_down_sync(0xffffffffu, s, o);
    if (!lane) g_cc[c] = s;
}

// ---------------- kernel: fragment-ordered tf32 (hi) codebook ---------------
// idx bits = layer(3) | jb(3) | c8(5) | p(3) | lane(5)   (total 19 -> 524288)
// element e of float4: nt = 2p + (e>>1); b-reg = e&1 (k 0..3 / 4..7).
__global__ void cbfrag_prep(const float* __restrict__ cbs) {
    const unsigned idx = blockIdx.x * 256 + threadIdx.x;   // 0 .. 524287
    const int lane  = idx & 31;
    const int p     = (idx >> 5) & 7;
    const int c8    = (idx >> 8) & 31;
    const int jb    = (idx >> 13) & 7;
    const int layer = (int)(idx >> 16);
    float4 o;
    float* oe = &o.x;
#pragma unroll
    for (int e = 0; e < 4; e++) {
        const int nt = 2 * p + (e >> 1);
        const int j  = jb * 128 + nt * 8 + (lane >> 2);
        const int k  = c8 * 8 + (lane & 3) + ((e & 1) ? 4 : 0);
        const float x = cbs[((size_t)layer * NBINS + j) * Dd + k];
        oe[e] = __uint_as_float(f2tf(x));
    }
    g_cbfrag[idx] = o;
}

// ---------------- top-4 sorted insert ----------------------------------------
__device__ __forceinline__ void top4_upd(float v[4], int j[4], float nv, int nj) {
    if (!(nv < v[3] || (nv == v[3] && nj < j[3]))) return;
    if (nv < v[0] || (nv == v[0] && nj < j[0])) {
        v[3] = v[2]; j[3] = j[2]; v[2] = v[1]; j[2] = j[1];
        v[1] = v[0]; j[1] = j[0]; v[0] = nv;   j[0] = nj;
    } else if (nv < v[1] || (nv == v[1] && nj < j[1])) {
        v[3] = v[2]; j[3] = j[2]; v[2] = v[1]; j[2] = j[1];
        v[1] = nv;   j[1] = nj;
    } else if (nv < v[2] || (nv == v[2] && nj < j[2])) {
        v[3] = v[2]; j[3] = j[2]; v[2] = nv;   j[2] = nj;
    } else {
        v[3] = nv;   j[3] = nj;
    }
}

// ---------------- kernel: one RVQ layer (tensor-core) ------------------------
__global__ __launch_bounds__(NTH, 1)
void rvq_layer_kernel(const float* __restrict__ cb,   // layer codebook [1024][256]
                      int layer,
                      float* __restrict__ codes_out)
{
    extern __shared__ float4 sm4[];
    float4* Af4 = sm4;                 // [8 mb][32 c8][32 lane] (tf32-rounded)
    float4* Bs4 = sm4 + AF4;           // [2 buf][4 c8][8 p][32 lane]
    float*  ccs   = (float*)(sm4 + AF4 + 2 * BS4);   // [128]
    float*  s_v   = ccs + 128;                       // [2][128][4]
    int*    s_j   = (int*)(s_v + 1024);              // [2][128][4]
    int*    cand4 = s_j + 1024;                      // [128][4]
    int*    sidx  = cand4 + 512;                     // [128]
    float*  wloss = (float*)(sidx + 128);            // [8]

    const int tid  = threadIdx.x;
    const int wid  = tid >> 5;
    const int lane = tid & 31;
    const int ms   = wid & 3;    // m-strip (32 rows each)
    const int jh   = wid >> 2;   // j-half within a 128-j tile
    const int n0   = blockIdx.x * MTILE;
    const float* ccL = g_cc + layer * NBINS;

    // ---- A fragment load, pre-rounded to tf32 ----
    for (int pr = wid * 32; pr < wid * 32 + 32; pr++) {
        const int mb = pr >> 5, c8 = pr & 31;
        const float* r0 = g_resid + (size_t)(n0 + mb * 16 + (lane >> 2)) * Dd
                         + c8 * 8 + (lane & 3);
        const float* r1 = r0 + 8 * Dd;
        float4 raw = make_float4(r0[0], r1[0], r0[4], r1[4]);
        raw.x = __uint_as_float(f2tf(raw.x));
        raw.y = __uint_as_float(f2tf(raw.y));
        raw.z = __uint_as_float(f2tf(raw.z));
        raw.w = __uint_as_float(f2tf(raw.w));
        Af4[pr * 32 + lane] = raw;
    }

    float bestv[4][4];
    int   bestj[4][4];
#pragma unroll
    for (int s = 0; s < 4; s++)
#pragma unroll
        for (int c = 0; c < 4; c++) { bestv[s][c] = 3.402823466e38f; bestj[s][c] = 0x7fffffff; }
    __syncthreads();

    // ---- 8 j-tiles of 128 codes ----
#pragma unroll 1
    for (int jt = 0; jt < 8; jt++) {
        const int j0 = jt * 128;
        const unsigned gbase = ((unsigned)layer * 8 + jt) * 8192u;

        float acc[2][8][4];
#pragma unroll
        for (int mt = 0; mt < 2; mt++)
#pragma unroll
            for (int nt = 0; nt < 8; nt++)
#pragma unroll
                for (int c = 0; c < 4; c++) acc[mt][nt][c] = 0.f;

        if (tid < 128) ccs[tid] = ccL[j0 + tid];

        // prologue: chunk 0 (c8 0..3) -> buffer 0
#pragma unroll
        for (int i = 0; i < 4; i++)
            Bs4[i * 256 + tid] = g_cbfrag[gbase + i * 256 + tid];
        __syncthreads();

#pragma unroll 1
        for (int ch = 0; ch < 8; ch++) {
            float4 pf[4];
            if (ch < 7) {
                const unsigned src = gbase + (unsigned)(ch + 1) * 1024u;
#pragma unroll
                for (int i = 0; i < 4; i++) pf[i] = g_cbfrag[src + i * 256 + tid];
            }
            const float4* bbuf = Bs4 + (ch & 1) * BS4;
#pragma unroll
            for (int k8 = 0; k8 < 4; k8++) {
                const int c8 = ch * 4 + k8;
                const uint4 a0 = *(const uint4*)&Af4[((ms * 2 + 0) * 32 + c8) * 32 + lane];
                const uint4 a1 = *(const uint4*)&Af4[((ms * 2 + 1) * 32 + c8) * 32 + lane];
#pragma unroll
                for (int p = 0; p < 4; p++) {
                    const uint4 bh = *(const uint4*)&bbuf[k8 * 256 + (jh * 4 + p) * 32 + lane];
                    mma_tf32(acc[0][2 * p],     a0.x, a0.y, a0.z, a0.w, bh.x, bh.y);
                    mma_tf32(acc[0][2 * p + 1], a0.x, a0.y, a0.z, a0.w, bh.z, bh.w);
                    mma_tf32(acc[1][2 * p],     a1.x, a1.y, a1.z, a1.w, bh.x, bh.y);
                    mma_tf32(acc[1][2 * p + 1], a1.x, a1.y, a1.z, a1.w, bh.z, bh.w);
                }
            }
            if (ch < 7) {
                float4* dst = Bs4 + ((ch + 1) & 1) * BS4;
#pragma unroll
                for (int i = 0; i < 4; i++) dst[i * 256 + tid] = pf[i];
            }
            __syncthreads();
        }

        // epilogue: approx dists (rr omitted: row-constant), per-slot top-4.
        // D frag: c0->(g,2t) c1->(g,2t+1) c2->(g+8,2t) c3->(g+8,2t+1)
#pragma unroll
        for (int mt = 0; mt < 2; mt++)
#pragma unroll
            for (int nt = 0; nt < 8; nt++) {
                const int jl = jh * 64 + nt * 8 + 2 * (lane & 3);
                const int j  = j0 + jl;
                const float d0 = fmaf(-2.f, acc[mt][nt][0], ccs[jl]);
                const float d1 = fmaf(-2.f, acc[mt][nt][1], ccs[jl + 1]);
                const float d2 = fmaf(-2.f, acc[mt][nt][2], ccs[jl]);
                const float d3 = fmaf(-2.f, acc[mt][nt][3], ccs[jl + 1]);
                top4_upd(bestv[2 * mt],     bestj[2 * mt],     d0, j);
                top4_upd(bestv[2 * mt],     bestj[2 * mt],     d1, j + 1);
                top4_upd(bestv[2 * mt + 1], bestj[2 * mt + 1], d2, j);
                top4_upd(bestv[2 * mt + 1], bestj[2 * mt + 1], d3, j + 1);
            }
        __syncthreads();   // ccs/Bs reuse across jt
    }

    // ---- merge top-4 across the 4 lanes sharing a row (snapshot then insert)
#pragma unroll
    for (int s = 0; s < 4; s++) {
#pragma unroll
        for (int off = 1; off <= 2; off <<= 1) {
            float ov[4]; int oj[4];
#pragma unroll
            for (int c = 0; c < 4; c++) {
                ov[c] = __shfl_xor_sync(0xffffffffu, bestv[s][c], off);
                oj[c] = __shfl_xor_sync(0xffffffffu, bestj[s][c], off);
            }
#pragma unroll
            for (int c = 0; c < 4; c++) top4_upd(bestv[s], bestj[s], ov[c], oj[c]);
        }
        if ((lane & 3) == 0) {
            const int r = ms * 32 + (s >> 1) * 16 + (s & 1) * 8 + (lane >> 2);
#pragma unroll
            for (int c = 0; c < 4; c++) {
                s_v[(jh * 128 + r) * 4 + c] = bestv[s][c];
                s_j[(jh * 128 + r) * 4 + c] = bestj[s][c];
            }
        }
    }
    __syncthreads();

    // ---- merge the two j-halves per row -> 4 candidates ----
    if (tid < 128) {
        float v[4]; int j[4];
#pragma unroll
        for (int c = 0; c < 4; c++) { v[c] = s_v[tid * 4 + c]; j[c] = s_j[tid * 4 + c]; }
#pragma unroll
        for (int c = 0; c < 4; c++)
            top4_upd(v, j, s_v[(128 + tid) * 4 + c], s_j[(128 + tid) * 4 + c]);
#pragma unroll
        for (int c = 0; c < 4; c++) cand4[tid * 4 + c] = j[c];
    }
    __syncthreads();

    // ---- exact fp32 refine of the 4 candidates (1 warp : 16 rows) ----
    for (int i = 0; i < 16; i++) {
        const int r = wid * 16 + i;
        const int j0c = cand4[r * 4 + 0], j1c = cand4[r * 4 + 1];
        const int j2c = cand4[r * 4 + 2], j3c = cand4[r * 4 + 3];
        const float* rv = g_resid + (size_t)(n0 + r) * Dd;
        const float* c0 = cb + (size_t)j0c * Dd;
        const float* c1 = cb + (size_t)j1c * Dd;
        const float* c2 = cb + (size_t)j2c * Dd;
        const float* c3 = cb + (size_t)j3c * Dd;
        float s0 = 0.f, s1 = 0.f, s2 = 0.f, s3 = 0.f;
#pragma unroll
        for (int kq = 0; kq < 8; kq++) {
            const float rvx = rv[kq * 32 + lane];
            s0 = fmaf(rvx, c0[kq * 32 + lane], s0);
            s1 = fmaf(rvx, c1[kq * 32 + lane], s1);
            s2 = fmaf(rvx, c2[kq * 32 + lane], s2);
            s3 = fmaf(rvx, c3[kq * 32 + lane], s3);
        }
#pragma unroll
        for (int o = 16; o; o >>= 1) {
            s0 += __shfl_down_sync(0xffffffffu, s0, o);
            s1 += __shfl_down_sync(0xffffffffu, s1, o);
            s2 += __shfl_down_sync(0xffffffffu, s2, o);
            s3 += __shfl_down_sync(0xffffffffu, s3, o);
        }
        if (!lane) {
            const float rrn = g_rr[n0 + r];
            float bd = fmaf(-2.f, s0, rrn) + ccL[j0c];
            int   bj = j0c;
            float d;
            d = fmaf(-2.f, s1, rrn) + ccL[j1c];
            if (d < bd || (d == bd && j1c < bj)) { bd = d; bj = j1c; }
            d = fmaf(-2.f, s2, rrn) + ccL[j2c];
            if (d < bd || (d == bd && j2c < bj)) { bd = d; bj = j2c; }
            d = fmaf(-2.f, s3, rrn) + ccL[j3c];
            if (d < bd || (d == bd && j3c < bj)) { bd = d; bj = j3c; }
            sidx[r] = bj;
        }
    }
    __syncthreads();

    // ---- fused update: resid -= cb[idx]; new norms; codes; loss ----
    float wl = 0.f;
    for (int m = wid; m < MTILE; m += 8) {
        const int j = sidx[m];
        const float* q = cb + (size_t)j * Dd;
        float* rout = g_resid + (size_t)(n0 + m) * Dd;
        float s = 0.f;
#pragma unroll
        for (int i = 0; i < 8; i++) {
            const int d = i * 32 + lane;
            const float rn = rout[d] - q[d];
            rout[d] = rn;
            s = fmaf(rn, rn, s);
        }
#pragma unroll
        for (int o = 16; o; o >>= 1) s += __shfl_down_sync(0xffffffffu, s, o);
        if (!lane) {
            g_rr[n0 + m] = s;
            wl += s;
            if (codes_out) codes_out[(size_t)layer * NVEC + n0 + m] = (float)j;
        }
    }
    if (!lane) wloss[wid] = wl;
    __syncthreads();
    if (tid == 0) {
        float t = 0.f;
#pragma unroll
        for (int w = 0; w < 8; w++) t += wloss[w];
        g_losspart[layer * GRID_L + blockIdx.x] = t;
    }
}

// ---------------- kernel: quantized = x - resid_final, + loss ---------------
__global__ void finalize_kernel(const float* __restrict__ x,
                                float* __restrict__ out,
                                float* __restrict__ loss_dst) {
    __shared__ float tile[32][33];
    const int b  = blockIdx.z;
    const int d0 = blockIdx.y * 32;
    const int t0 = blockIdx.x * 32;
    const int tx = threadIdx.x, ty = threadIdx.y;
#pragma unroll
    for (int i = 0; i < 32; i += 8)
        tile[ty + i][tx] = g_resid[(size_t)(b * Tt + t0 + ty + i) * Dd + d0 + tx];
    __syncthreads();
#pragma unroll
    for (int i = 0; i < 32; i += 8) {
        const size_t idx = (size_t)b * Dd * Tt + (size_t)(d0 + ty + i) * Tt + t0 + tx;
        out[idx] = x[idx] - tile[tx][ty + i];
    }
    if (loss_dst && blockIdx.x == 0 && blockIdx.y == 0 && blockIdx.z == 0 && ty == 0) {
        double s = 0.0;
        for (int i = tx; i < NQ * GRID_L; i += 32) s += (double)g_losspart[i];
#pragma unroll
        for (int o = 16; o; o >>= 1) s += __shfl_down_sync(0xffffffffu, s, o);
        if (tx == 0)
            *loss_dst = (float)(s / ((double)NQ * (double)NVEC * (double)Dd));
    }
}

// ---------------- launch -----------------------------------------------------
extern "C" void kernel_launch(void* const* d_in, const int* in_sizes, int n_in,
                              void* d_out, int out_size) {
    const float* x   = (const float*)d_in[0];
    const float* cbs = (const float*)d_in[1];
    float* out = (float*)d_out;

    const long long QN = (long long)Bb * Dd * Tt;
    const long long CN = (long long)NQ * Bb * Tt;
    float* codes = ((long long)out_size >= QN + CN) ? out + QN : nullptr;
    float* lossp = ((long long)out_size >= QN + CN + 1) ? out + QN + CN : nullptr;

    cudaFuncSetAttribute(rvq_layer_kernel,
                         cudaFuncAttributeMaxDynamicSharedMemorySize,
                         SMEM_BYTES_L);

    transpose_in_kernel<<<dim3(Tt / 32, Dd / 32, Bb), dim3(32, 8)>>>(x);
    rownorm_kernel<<<NVEC / 8, 256>>>();
    codenorm_kernel<<<NQ * NBINS / 8, 256>>>(cbs);
    cbfrag_prep<<<2048, 256>>>(cbs);
    for (int l = 0; l < NQ; l++) {
        rvq_layer_kernel<<<GRID_L, NTH, SMEM_BYTES_L>>>(
            cbs + (size_t)l * NBINS * Dd, l, codes);
    }
    finalize_kernel<<<dim3(Tt / 32, Dd / 32, Bb), dim3(32, 8)>>>(x, out, lossp);
}

// round 12
// speedup vs baseline: 2.2659x; 1.5493x over previous
#include <cuda_runtime.h>

// ---------------------------------------------------------------------------
// RVQ, 8 layers. R11: MTILE=64 -> 2 CTAs/SM (4 warps/SMSP) to overlap the
//  exposed non-tensor cost; branchless top-4 via sortable u64 keys.
//  Single-pass tf32 mma + exact fp32 re-rank of 4 candidates (reference math).
// ---------------------------------------------------------------------------

namespace {
constexpr int Bb    = 16;
constexpr int Dd    = 256;
constexpr int Tt    = 4096;
constexpr int NQ    = 8;
constexpr int NBINS = 1024;
constexpr int NVEC  = Bb * Tt;        // 65536
constexpr int MTILE = 64;
constexpr int GRID_L = NVEC / MTILE;  // 1024
constexpr int NTH   = 256;

constexpr int AF4 = 4096;             // A frags: 4 mb x 32 c8 x 32 lanes (float4)
constexpr int BS4 = 1024;             // per buffer: 4 c8 x 8 p x 32 lanes (hi only)
constexpr int SMEM_BYTES_L = (AF4 + 2 * BS4) * 16   // 98304
                           + 128 * 4                // ccs
                           + 2 * 64 * 4 * 8         // s_k  [2][64][4] u64
                           + 64 * 4 * 4             // cand4 [64][4]
                           + 64 * 4                 // sidx
                           + 64;                    // wloss + pad => 104256
}

// ---------------- device scratch --------------------------------------------
__device__ __align__(16) float  g_resid[(size_t)NVEC * Dd];     // 64 MB
__device__ __align__(16) float  g_rr[NVEC];
__device__ __align__(16) float  g_cc[NQ * NBINS];
__device__ __align__(16) float  g_losspart[NQ * GRID_L];
__device__ __align__(16) float4 g_cbfrag[524288];               // 8 MB hi frags

// ---------------- helpers ----------------------------------------------------
__device__ __forceinline__ unsigned f2tf(float x) {
    unsigned r;
    asm("cvt.rna.tf32.f32 %0, %1;" : "=r"(r) : "f"(x));
    return r;
}
__device__ __forceinline__ void mma_tf32(float* d,
                                         unsigned a0, unsigned a1, unsigned a2, unsigned a3,
                                         unsigned b0, unsigned b1) {
    asm volatile(
        "mma.sync.aligned.m16n8k8.row.col.f32.tf32.tf32.f32 "
        "{%0,%1,%2,%3},{%4,%5,%6,%7},{%8,%9},{%0,%1,%2,%3};"
        : "+f"(d[0]), "+f"(d[1]), "+f"(d[2]), "+f"(d[3])
        : "r"(a0), "r"(a1), "r"(a2), "r"(a3), "r"(b0), "r"(b1));
}
// order-preserving (dist, j) key: smaller dist first, then smaller j
__device__ __forceinline__ unsigned long long dkey(float d, int j) {
    unsigned u = __float_as_uint(d);
    u ^= ((unsigned)((int)u >> 31)) | 0x80000000u;
    return ((unsigned long long)u << 32) | (unsigned)j;
}
__device__ __forceinline__ unsigned long long umin64(unsigned long long a,
                                                     unsigned long long b) {
    return a < b ? a : b;
}
__device__ __forceinline__ unsigned long long umax64(unsigned long long a,
                                                     unsigned long long b) {
    return a < b ? b : a;
}
// branchless sorted insert into ascending k[0..3]
__device__ __forceinline__ void top4_ins(unsigned long long k[4],
                                         unsigned long long x) {
    unsigned long long t;
    t = umin64(k[0], x); x = umax64(k[0], x); k[0] = t;
    t = umin64(k[1], x); x = umax64(k[1], x); k[1] = t;
    t = umin64(k[2], x); x = umax64(k[2], x); k[2] = t;
    k[3] = umin64(k[3], x);
}

// ---------------- kernel: transpose x[B,D,T] -> resid[n][d] -----------------
__global__ void transpose_in_kernel(const float* __restrict__ x) {
    __shared__ float tile[32][33];
    const int b  = blockIdx.z;
    const int d0 = blockIdx.y * 32;
    const int t0 = blockIdx.x * 32;
    const int tx = threadIdx.x, ty = threadIdx.y;
    const float* xb = x + (size_t)b * Dd * Tt;
#pragma unroll
    for (int i = 0; i < 32; i += 8)
        tile[ty + i][tx] = xb[(size_t)(d0 + ty + i) * Tt + t0 + tx];
    __syncthreads();
#pragma unroll
    for (int i = 0; i < 32; i += 8) {
        const int t = t0 + ty + i;
        g_resid[(size_t)(b * Tt + t) * Dd + d0 + tx] = tile[tx][ty + i];
    }
}

// ---------------- kernel: row squared norms ---------------------------------
__global__ void rownorm_kernel() {
    const int row  = blockIdx.x * 8 + (threadIdx.x >> 5);
    const int lane = threadIdx.x & 31;
    const float* r = g_resid + (size_t)row * Dd;
    float s = 0.f;
#pragma unroll
    for (int i = 0; i < 8; i++) { float v = r[i * 32 + lane]; s = fmaf(v, v, s); }
#pragma unroll
    for (int o = 16; o; o >>= 1) s += __shfl_down_sync(0xffffffffu, s, o);
    if (!lane) g_rr[row] = s;
}

// ---------------- kernel: codebook squared norms ----------------------------
__global__ void codenorm_kernel(const float* __restrict__ cbs) {
    const int c    = blockIdx.x * 8 + (threadIdx.x >> 5);
    const int lane = threadIdx.x & 31;
    const float* r = cbs + (size_t)c * Dd;
    float s = 0.f;
#pragma unroll
    for (int i = 0; i < 8; i++) { float v = r[i * 32 + lane]; s = fmaf(v, v, s); }
#pragma unroll
    for (int o = 16; o; o >>= 1) s += __shfl_down_sync(0xffffffffu, s, o);
    if (!lane) g_cc[c] = s;
}

// ---------------- kernel: fragment-ordered tf32 (hi) codebook ---------------
// idx bits = layer(3) | jb(3) | c8(5) | p(3) | lane(5)
__global__ void cbfrag_prep(const float* __restrict__ cbs) {
    const unsigned idx = blockIdx.x * 256 + threadIdx.x;   // 0 .. 524287
    const int lane  = idx & 31;
    const int p     = (idx >> 5) & 7;
    const int c8    = (idx >> 8) & 31;
    const int jb    = (idx >> 13) & 7;
    const int layer = (int)(idx >> 16);
    float4 o;
    float* oe = &o.x;
#pragma unroll
    for (int e = 0; e < 4; e++) {
        const int nt = 2 * p + (e >> 1);
        const int j  = jb * 128 + nt * 8 + (lane >> 2);
        const int k  = c8 * 8 + (lane & 3) + ((e & 1) ? 4 : 0);
        const float x = cbs[((size_t)layer * NBINS + j) * Dd + k];
        oe[e] = __uint_as_float(f2tf(x));
    }
    g_cbfrag[idx] = o;
}

// ---------------- kernel: one RVQ layer (tensor-core) ------------------------
__global__ __launch_bounds__(NTH, 2)
void rvq_layer_kernel(const float* __restrict__ cb,   // layer codebook [1024][256]
                      int layer,
                      float* __restrict__ codes_out)
{
    extern __shared__ float4 sm4[];
    float4* Af4 = sm4;                 // [4 mb][32 c8][32 lane] (tf32-rounded)
    float4* Bs4 = sm4 + AF4;           // [2 buf][4 c8][8 p][32 lane]
    float*  ccs   = (float*)(sm4 + AF4 + 2 * BS4);               // [128]
    unsigned long long* s_k = (unsigned long long*)(ccs + 128);  // [2][64][4]
    int*    cand4 = (int*)(s_k + 512);                           // [64][4]
    int*    sidx  = cand4 + 256;                                 // [64]
    float*  wloss = (float*)(sidx + 64);                         // [8]

    const int tid  = threadIdx.x;
    const int wid  = tid >> 5;
    const int lane = tid & 31;
    const int mb   = wid >> 1;   // 0..3 : 16-row block
    const int jh   = wid & 1;    // 0..1 : j-half within a 128-j tile
    const int n0   = blockIdx.x * MTILE;
    const float* ccL = g_cc + layer * NBINS;

    // ---- A fragment load, pre-rounded to tf32 ----
    for (int pr = wid * 16; pr < wid * 16 + 16; pr++) {
        const int pmb = pr >> 5, c8 = pr & 31;
        const float* r0 = g_resid + (size_t)(n0 + pmb * 16 + (lane >> 2)) * Dd
                         + c8 * 8 + (lane & 3);
        const float* r1 = r0 + 8 * Dd;
        float4 raw = make_float4(r0[0], r1[0], r0[4], r1[4]);
        raw.x = __uint_as_float(f2tf(raw.x));
        raw.y = __uint_as_float(f2tf(raw.y));
        raw.z = __uint_as_float(f2tf(raw.z));
        raw.w = __uint_as_float(f2tf(raw.w));
        Af4[pr * 32 + lane] = raw;
    }

    unsigned long long bk[2][4];     // slot 0: row g; slot 1: row g+8
#pragma unroll
    for (int s = 0; s < 2; s++)
#pragma unroll
        for (int c = 0; c < 4; c++) bk[s][c] = 0xFFFFFFFFFFFFFFFFULL;
    __syncthreads();

    // ---- 8 j-tiles of 128 codes ----
#pragma unroll 1
    for (int jt = 0; jt < 8; jt++) {
        const int j0 = jt * 128;
        const unsigned gbase = ((unsigned)layer * 8 + jt) * 8192u;

        float acc[8][4];
#pragma unroll
        for (int nt = 0; nt < 8; nt++)
#pragma unroll
            for (int c = 0; c < 4; c++) acc[nt][c] = 0.f;

        if (tid < 128) ccs[tid] = ccL[j0 + tid];

        // prologue: chunk 0 (c8 0..3) -> buffer 0
#pragma unroll
        for (int i = 0; i < 4; i++)
            Bs4[i * 256 + tid] = g_cbfrag[gbase + i * 256 + tid];
        __syncthreads();

#pragma unroll 1
        for (int ch = 0; ch < 8; ch++) {
            float4 pf[4];
            if (ch < 7) {
                const unsigned src = gbase + (unsigned)(ch + 1) * 1024u;
#pragma unroll
                for (int i = 0; i < 4; i++) pf[i] = g_cbfrag[src + i * 256 + tid];
            }
            const float4* bbuf = Bs4 + (ch & 1) * BS4;
#pragma unroll
            for (int k8 = 0; k8 < 4; k8++) {
                const int c8 = ch * 4 + k8;
                const uint4 a = *(const uint4*)&Af4[(mb * 32 + c8) * 32 + lane];
#pragma unroll
                for (int p = 0; p < 4; p++) {
                    const uint4 bh = *(const uint4*)&bbuf[k8 * 256 + (jh * 4 + p) * 32 + lane];
                    mma_tf32(acc[2 * p],     a.x, a.y, a.z, a.w, bh.x, bh.y);
                    mma_tf32(acc[2 * p + 1], a.x, a.y, a.z, a.w, bh.z, bh.w);
                }
            }
            if (ch < 7) {
                float4* dst = Bs4 + ((ch + 1) & 1) * BS4;
#pragma unroll
                for (int i = 0; i < 4; i++) dst[i * 256 + tid] = pf[i];
            }
            __syncthreads();
        }

        // epilogue: approx dists (rr omitted: row-constant), branchless top-4.
        // D frag: c0->(g,2t) c1->(g,2t+1) c2->(g+8,2t) c3->(g+8,2t+1)
#pragma unroll
        for (int nt = 0; nt < 8; nt++) {
            const int jl = jh * 64 + nt * 8 + 2 * (lane & 3);
            const int j  = j0 + jl;
            const float d0 = fmaf(-2.f, acc[nt][0], ccs[jl]);
            const float d1 = fmaf(-2.f, acc[nt][1], ccs[jl + 1]);
            const float d2 = fmaf(-2.f, acc[nt][2], ccs[jl]);
            const float d3 = fmaf(-2.f, acc[nt][3], ccs[jl + 1]);
            top4_ins(bk[0], dkey(d0, j));
            top4_ins(bk[0], dkey(d1, j + 1));
            top4_ins(bk[1], dkey(d2, j));
            top4_ins(bk[1], dkey(d3, j + 1));
        }
        __syncthreads();   // ccs/Bs reuse across jt
    }

    // ---- merge top-4 across the 4 lanes sharing a row ----
#pragma unroll
    for (int s = 0; s < 2; s++) {
#pragma unroll
        for (int off = 1; off <= 2; off <<= 1) {
            unsigned long long ok[4];
#pragma unroll
            for (int c = 0; c < 4; c++)
                ok[c] = __shfl_xor_sync(0xffffffffu, bk[s][c], off);
#pragma unroll
            for (int c = 0; c < 4; c++) top4_ins(bk[s], ok[c]);
        }
        if ((lane & 3) == 0) {
            const int r = mb * 16 + s * 8 + (lane >> 2);
#pragma unroll
            for (int c = 0; c < 4; c++)
                s_k[(jh * 64 + r) * 4 + c] = bk[s][c];
        }
    }
    __syncthreads();

    // ---- merge the two j-halves per row -> 4 candidate j's ----
    if (tid < 64) {
        unsigned long long k[4];
#pragma unroll
        for (int c = 0; c < 4; c++) k[c] = s_k[tid * 4 + c];
#pragma unroll
        for (int c = 0; c < 4; c++) top4_ins(k, s_k[(64 + tid) * 4 + c]);
#pragma unroll
        for (int c = 0; c < 4; c++) cand4[tid * 4 + c] = (int)(unsigned)k[c];
    }
    __syncthreads();

    // ---- exact fp32 refine of the 4 candidates (1 warp : 8 rows) ----
    for (int i = 0; i < 8; i++) {
        const int r = wid * 8 + i;
        const int j0c = cand4[r * 4 + 0], j1c = cand4[r * 4 + 1];
        const int j2c = cand4[r * 4 + 2], j3c = cand4[r * 4 + 3];
        const float* rv = g_resid + (size_t)(n0 + r) * Dd;
        const float* c0 = cb + (size_t)j0c * Dd;
        const float* c1 = cb + (size_t)j1c * Dd;
        const float* c2 = cb + (size_t)j2c * Dd;
        const float* c3 = cb + (size_t)j3c * Dd;
        float s0 = 0.f, s1 = 0.f, s2 = 0.f, s3 = 0.f;
#pragma unroll
        for (int kq = 0; kq < 8; kq++) {
            const float rvx = rv[kq * 32 + lane];
            s0 = fmaf(rvx, c0[kq * 32 + lane], s0);
            s1 = fmaf(rvx, c1[kq * 32 + lane], s1);
            s2 = fmaf(rvx, c2[kq * 32 + lane], s2);
            s3 = fmaf(rvx, c3[kq * 32 + lane], s3);
        }
#pragma unroll
        for (int o = 16; o; o >>= 1) {
            s0 += __shfl_down_sync(0xffffffffu, s0, o);
            s1 += __shfl_down_sync(0xffffffffu, s1, o);
            s2 += __shfl_down_sync(0xffffffffu, s2, o);
            s3 += __shfl_down_sync(0xffffffffu, s3, o);
        }
        if (!lane) {
            const float rrn = g_rr[n0 + r];
            float bd = fmaf(-2.f, s0, rrn) + ccL[j0c];
            int   bj = j0c;
            float d;
            d = fmaf(-2.f, s1, rrn) + ccL[j1c];
            if (d < bd || (d == bd && j1c < bj)) { bd = d; bj = j1c; }
            d = fmaf(-2.f, s2, rrn) + ccL[j2c];
            if (d < bd || (d == bd && j2c < bj)) { bd = d; bj = j2c; }
            d = fmaf(-2.f, s3, rrn) + ccL[j3c];
            if (d < bd || (d == bd && j3c < bj)) { bd = d; bj = j3c; }
            sidx[r] = bj;
        }
    }
    __syncthreads();

    // ---- fused update: resid -= cb[idx]; new norms; codes; loss ----
    float wl = 0.f;
    for (int m = wid; m < MTILE; m += 8) {
        const int j = sidx[m];
        const float* q = cb + (size_t)j * Dd;
        float* rout = g_resid + (size_t)(n0 + m) * Dd;
        float s = 0.f;
#pragma unroll
        for (int i = 0; i < 8; i++) {
            const int d = i * 32 + lane;
            const float rn = rout[d] - q[d];
            rout[d] = rn;
            s = fmaf(rn, rn, s);
        }
#pragma unroll
        for (int o = 16; o; o >>= 1) s += __shfl_down_sync(0xffffffffu, s, o);
        if (!lane) {
            g_rr[n0 + m] = s;
            wl += s;
            if (codes_out) codes_out[(size_t)layer * NVEC + n0 + m] = (float)j;
        }
    }
    if (!lane) wloss[wid] = wl;
    __syncthreads();
    if (tid == 0) {
        float t = 0.f;
#pragma unroll
        for (int w = 0; w < 8; w++) t += wloss[w];
        g_losspart[layer * GRID_L + blockIdx.x] = t;
    }
}

// ---------------- kernel: quantized = x - resid_final, + loss ---------------
__global__ void finalize_kernel(const float* __restrict__ x,
                                float* __restrict__ out,
                                float* __restrict__ loss_dst) {
    __shared__ float tile[32][33];
    const int b  = blockIdx.z;
    const int d0 = blockIdx.y * 32;
    const int t0 = blockIdx.x * 32;
    const int tx = threadIdx.x, ty = threadIdx.y;
#pragma unroll
    for (int i = 0; i < 32; i += 8)
        tile[ty + i][tx] = g_resid[(size_t)(b * Tt + t0 + ty + i) * Dd + d0 + tx];
    __syncthreads();
#pragma unroll
    for (int i = 0; i < 32; i += 8) {
        const size_t idx = (size_t)b * Dd * Tt + (size_t)(d0 + ty + i) * Tt + t0 + tx;
        out[idx] = x[idx] - tile[tx][ty + i];
    }
    if (loss_dst && blockIdx.x == 0 && blockIdx.y == 0 && blockIdx.z == 0 && ty == 0) {
        double s = 0.0;
        for (int i = tx; i < NQ * GRID_L; i += 32) s += (double)g_losspart[i];
#pragma unroll
        for (int o = 16; o; o >>= 1) s += __shfl_down_sync(0xffffffffu, s, o);
        if (tx == 0)
            *loss_dst = (float)(s / ((double)NQ * (double)NVEC * (double)Dd));
    }
}

// ---------------- launch -----------------------------------------------------
extern "C" void kernel_launch(void* const* d_in, const int* in_sizes, int n_in,
                              void* d_out, int out_size) {
    const float* x   = (const float*)d_in[0];
    const float* cbs = (const float*)d_in[1];
    float* out = (float*)d_out;

    const long long QN = (long long)Bb * Dd * Tt;
    const long long CN = (long long)NQ * Bb * Tt;
    float* codes = ((long long)out_size >= QN + CN) ? out + QN : nullptr;
    float* lossp = ((long long)out_size >= QN + CN + 1) ? out + QN + CN : nullptr;

    cudaFuncSetAttribute(rvq_layer_kernel,
                         cudaFuncAttributeMaxDynamicSharedMemorySize,
                         SMEM_BYTES_L);

    transpose_in_kernel<<<dim3(Tt / 32, Dd / 32, Bb), dim3(32, 8)>>>(x);
    rownorm_kernel<<<NVEC / 8, 256>>>();
    codenorm_kernel<<<NQ * NBINS / 8, 256>>>(cbs);
    cbfrag_prep<<<2048, 256>>>(cbs);
    for (int l = 0; l < NQ; l++) {
        rvq_layer_kernel<<<GRID_L, NTH, SMEM_BYTES_L>>>(
            cbs + (size_t)l * NBINS * Dd, l, codes);
    }
    finalize_kernel<<<dim3(Tt / 32, Dd / 32, Bb), dim3(32, 8)>>>(x, out, lossp);
}

// round 14
// speedup vs baseline: 3.2524x; 1.4354x over previous
#include <cuda_runtime.h>

// ---------------------------------------------------------------------------
// RVQ, 8 layers. R12 (resubmit after infra fail): bf16 m16n8k16 mma (K=16 per
//  instruction, 2x fewer mma than tf32 k8) + branchless top-4 (sortable u64
//  keys) + exact fp32 re-rank of the 4 candidates (reference math).
//  MTILE=64, 2 CTAs/SM.
// ---------------------------------------------------------------------------

namespace {
constexpr int Bb    = 16;
constexpr int Dd    = 256;
constexpr int Tt    = 4096;
constexpr int NQ    = 8;
constexpr int NBINS = 1024;
constexpr int NVEC  = Bb * Tt;        // 65536
constexpr int MTILE = 64;
constexpr int GRID_L = NVEC / MTILE;  // 1024
constexpr int NTH   = 256;

constexpr int AF4U = 2048;            // A frags: 4 mb x 16 c16 x 32 lanes (uint4)
constexpr int BS4U = 1024;            // per buffer: 4 c16 x 8 p x 32 lanes (uint4)
constexpr int SMEM_BYTES_L = (AF4U + 2 * BS4U) * 16  // 65536
                           + 128 * 4                 // ccs
                           + 512 * 8                 // s_k [2][64][4] u64
                           + 256 * 4                 // cand4 [64][4]
                           + 64 * 4                  // sidx
                           + 64;                     // wloss + pad => 71488
}

// ---------------- device scratch --------------------------------------------
__device__ __align__(16) float g_resid[(size_t)NVEC * Dd];      // 64 MB
__device__ __align__(16) float g_rr[NVEC];
__device__ __align__(16) float g_cc[NQ * NBINS];
__device__ __align__(16) float g_losspart[NQ * GRID_L];
__device__ __align__(16) uint4 g_cbfrag[262144];                // 4 MB bf16 frags

// ---------------- helpers ----------------------------------------------------
// pack two floats to bf16x2: low 16 bits = lo (even k), high = hi (odd k)
__device__ __forceinline__ unsigned pbf2(float lo, float hi) {
    unsigned r;
    asm("cvt.rn.bf16x2.f32 %0, %1, %2;" : "=r"(r) : "f"(hi), "f"(lo));
    return r;
}
__device__ __forceinline__ void mma_bf16(float* d,
                                         unsigned a0, unsigned a1, unsigned a2, unsigned a3,
                                         unsigned b0, unsigned b1) {
    asm volatile(
        "mma.sync.aligned.m16n8k16.row.col.f32.bf16.bf16.f32 "
        "{%0,%1,%2,%3},{%4,%5,%6,%7},{%8,%9},{%0,%1,%2,%3};"
        : "+f"(d[0]), "+f"(d[1]), "+f"(d[2]), "+f"(d[3])
        : "r"(a0), "r"(a1), "r"(a2), "r"(a3), "r"(b0), "r"(b1));
}
// order-preserving (dist, j) key: smaller dist first, then smaller j
__device__ __forceinline__ unsigned long long dkey(float d, int j) {
    unsigned u = __float_as_uint(d);
    u ^= ((unsigned)((int)u >> 31)) | 0x80000000u;
    return ((unsigned long long)u << 32) | (unsigned)j;
}
__device__ __forceinline__ unsigned long long umin64(unsigned long long a,
                                                     unsigned long long b) {
    return a < b ? a : b;
}
__device__ __forceinline__ unsigned long long umax64(unsigned long long a,
                                                     unsigned long long b) {
    return a < b ? b : a;
}
__device__ __forceinline__ void top4_ins(unsigned long long k[4],
                                         unsigned long long x) {
    unsigned long long t;
    t = umin64(k[0], x); x = umax64(k[0], x); k[0] = t;
    t = umin64(k[1], x); x = umax64(k[1], x); k[1] = t;
    t = umin64(k[2], x); x = umax64(k[2], x); k[2] = t;
    k[3] = umin64(k[3], x);
}

// ---------------- kernel: transpose x[B,D,T] -> resid[n][d] -----------------
__global__ void transpose_in_kernel(const float* __restrict__ x) {
    __shared__ float tile[32][33];
    const int b  = blockIdx.z;
    const int d0 = blockIdx.y * 32;
    const int t0 = blockIdx.x * 32;
    const int tx = threadIdx.x, ty = threadIdx.y;
    const float* xb = x + (size_t)b * Dd * Tt;
#pragma unroll
    for (int i = 0; i < 32; i += 8)
        tile[ty + i][tx] = xb[(size_t)(d0 + ty + i) * Tt + t0 + tx];
    __syncthreads();
#pragma unroll
    for (int i = 0; i < 32; i += 8) {
        const int t = t0 + ty + i;
        g_resid[(size_t)(b * Tt + t) * Dd + d0 + tx] = tile[tx][ty + i];
    }
}

// ---------------- kernel: row squared norms ---------------------------------
__global__ void rownorm_kernel() {
    const int row  = blockIdx.x * 8 + (threadIdx.x >> 5);
    const int lane = threadIdx.x & 31;
    const float* r = g_resid + (size_t)row * Dd;
    float s = 0.f;
#pragma unroll
    for (int i = 0; i < 8; i++) { float v = r[i * 32 + lane]; s = fmaf(v, v, s); }
#pragma unroll
    for (int o = 16; o; o >>= 1) s += __shfl_down_sync(0xffffffffu, s, o);
    if (!lane) g_rr[row] = s;
}

// ---------------- kernel: codebook squared norms ----------------------------
__global__ void codenorm_kernel(const float* __restrict__ cbs) {
    const int c    = blockIdx.x * 8 + (threadIdx.x >> 5);
    const int lane = threadIdx.x & 31;
    const float* r = cbs + (size_t)c * Dd;
    float s = 0.f;
#pragma unroll
    for (int i = 0; i < 8; i++) { float v = r[i * 32 + lane]; s = fmaf(v, v, s); }
#pragma unroll
    for (int o = 16; o; o >>= 1) s += __shfl_down_sync(0xffffffffu, s, o);
    if (!lane) g_cc[c] = s;
}

// ---------------- kernel: fragment-ordered bf16 codebook --------------------
// idx bits = layer(3) | jb(3) | c16(4) | p(3) | lane(5)   -> 262144
// uint4 element e: nt = 2p + (e>>1); breg r = e&1.
//  bf16x2: k = c16*16 + r*8 + 2*(lane&3) + {0(lo),1(hi)}, n = nt*8 + (lane>>2)
__global__ void cbfrag_prep(const float* __restrict__ cbs) {
    const unsigned idx = blockIdx.x * 256 + threadIdx.x;   // 0 .. 262143
    const int lane  = idx & 31;
    const int p     = (idx >> 5) & 7;
    const int c16   = (idx >> 8) & 15;
    const int jb    = (idx >> 12) & 7;
    const int layer = (int)(idx >> 15);
    uint4 o;
    unsigned* oe = &o.x;
#pragma unroll
    for (int e = 0; e < 4; e++) {
        const int nt = 2 * p + (e >> 1);
        const int r  = e & 1;
        const int j  = jb * 128 + nt * 8 + (lane >> 2);
        const int k  = c16 * 16 + r * 8 + 2 * (lane & 3);
        const float* src = cbs + ((size_t)layer * NBINS + j) * Dd + k;
        oe[e] = pbf2(src[0], src[1]);
    }
    g_cbfrag[idx] = o;
}

// ---------------- kernel: one RVQ layer (bf16 tensor-core) -------------------
__global__ __launch_bounds__(NTH, 2)
void rvq_layer_kernel(const float* __restrict__ cb,   // layer codebook [1024][256]
                      int layer,
                      float* __restrict__ codes_out)
{
    extern __shared__ uint4 smu[];
    uint4* Af4 = smu;                  // [4 mb][16 c16][32 lane]
    uint4* Bs4 = smu + AF4U;           // [2 buf][4 c16][8 p][32 lane]
    float* ccs   = (float*)(smu + AF4U + 2 * BS4U);              // [128]
    unsigned long long* s_k = (unsigned long long*)(ccs + 128);  // [2][64][4]
    int*   cand4 = (int*)(s_k + 512);                            // [64][4]
    int*   sidx  = cand4 + 256;                                  // [64]
    float* wloss = (float*)(sidx + 64);                          // [8]

    const int tid  = threadIdx.x;
    const int wid  = tid >> 5;
    const int lane = tid & 31;
    const int mb   = wid >> 1;   // 0..3 : 16-row block
    const int jh   = wid & 1;    // 0..1 : j-half within a 128-j tile
    const int n0   = blockIdx.x * MTILE;
    const float* ccL = g_cc + layer * NBINS;

    // ---- A fragment load, packed to bf16x2 (a0..a3 of m16n8k16) ----
    for (int pr = wid * 8; pr < wid * 8 + 8; pr++) {   // 64 (mb,c16) pairs / 8 warps
        const int pmb = pr >> 4, c16 = pr & 15;
        const float* base = g_resid
            + (size_t)(n0 + pmb * 16 + (lane >> 2)) * Dd
            + c16 * 16 + 2 * (lane & 3);
        const float2 v0 = *(const float2*)(base);            // (g,   k..k+1)
        const float2 v1 = *(const float2*)(base + 8 * Dd);   // (g+8, k..k+1)
        const float2 v2 = *(const float2*)(base + 8);        // (g,   k+8..9)
        const float2 v3 = *(const float2*)(base + 8 * Dd + 8);
        uint4 f;
        f.x = pbf2(v0.x, v0.y);
        f.y = pbf2(v1.x, v1.y);
        f.z = pbf2(v2.x, v2.y);
        f.w = pbf2(v3.x, v3.y);
        Af4[pr * 32 + lane] = f;
    }

    unsigned long long bk[2][4];     // slot 0: row g; slot 1: row g+8
#pragma unroll
    for (int s = 0; s < 2; s++)
#pragma unroll
        for (int c = 0; c < 4; c++) bk[s][c] = 0xFFFFFFFFFFFFFFFFULL;
    __syncthreads();

    // ---- 8 j-tiles of 128 codes ----
#pragma unroll 1
    for (int jt = 0; jt < 8; jt++) {
        const int j0 = jt * 128;
        const unsigned gbase = ((unsigned)layer * 8 + jt) * 4096u;

        float acc[8][4];
#pragma unroll
        for (int nt = 0; nt < 8; nt++)
#pragma unroll
            for (int c = 0; c < 4; c++) acc[nt][c] = 0.f;

        if (tid < 128) ccs[tid] = ccL[j0 + tid];

        // prologue: chunk 0 (c16 0..3) -> buffer 0
#pragma unroll
        for (int i = 0; i < 4; i++)
            Bs4[i * 256 + tid] = g_cbfrag[gbase + i * 256 + tid];
        __syncthreads();

#pragma unroll 1
        for (int ch = 0; ch < 4; ch++) {
            uint4 pf[4];
            if (ch < 3) {
                const unsigned src = gbase + (unsigned)(ch + 1) * 1024u;
#pragma unroll
                for (int i = 0; i < 4; i++) pf[i] = g_cbfrag[src + i * 256 + tid];
            }
            const uint4* bbuf = Bs4 + (ch & 1) * BS4U;
#pragma unroll
            for (int c16l = 0; c16l < 4; c16l++) {
                const int c16 = ch * 4 + c16l;
                const uint4 a = Af4[(mb * 16 + c16) * 32 + lane];
#pragma unroll
                for (int p = 0; p < 4; p++) {
                    const uint4 b = bbuf[(c16l * 8 + jh * 4 + p) * 32 + lane];
                    mma_bf16(acc[2 * p],     a.x, a.y, a.z, a.w, b.x, b.y);
                    mma_bf16(acc[2 * p + 1], a.x, a.y, a.z, a.w, b.z, b.w);
                }
            }
            if (ch < 3) {
                uint4* dst = Bs4 + ((ch + 1) & 1) * BS4U;
#pragma unroll
                for (int i = 0; i < 4; i++) dst[i * 256 + tid] = pf[i];
            }
            __syncthreads();
        }

        // epilogue: approx dists (rr omitted: row-constant), branchless top-4.
        // D frag: c0->(g,2t) c1->(g,2t+1) c2->(g+8,2t) c3->(g+8,2t+1)
#pragma unroll
        for (int nt = 0; nt < 8; nt++) {
            const int jl = jh * 64 + nt * 8 + 2 * (lane & 3);
            const int j  = j0 + jl;
            const float d0 = fmaf(-2.f, acc[nt][0], ccs[jl]);
            const float d1 = fmaf(-2.f, acc[nt][1], ccs[jl + 1]);
            const float d2 = fmaf(-2.f, acc[nt][2], ccs[jl]);
            const float d3 = fmaf(-2.f, acc[nt][3], ccs[jl + 1]);
            top4_ins(bk[0], dkey(d0, j));
            top4_ins(bk[0], dkey(d1, j + 1));
            top4_ins(bk[1], dkey(d2, j));
            top4_ins(bk[1], dkey(d3, j + 1));
        }
        __syncthreads();   // ccs/Bs reuse across jt
    }

    // ---- merge top-4 across the 4 lanes sharing a row ----
#pragma unroll
    for (int s = 0; s < 2; s++) {
#pragma unroll
        for (int off = 1; off <= 2; off <<= 1) {
            unsigned long long ok[4];
#pragma unroll
            for (int c = 0; c < 4; c++)
                ok[c] = __shfl_xor_sync(0xffffffffu, bk[s][c], off);
#pragma unroll
            for (int c = 0; c < 4; c++) top4_ins(bk[s], ok[c]);
        }
        if ((lane & 3) == 0) {
            const int r = mb * 16 + s * 8 + (lane >> 2);
#pragma unroll
            for (int c = 0; c < 4; c++)
                s_k[(jh * 64 + r) * 4 + c] = bk[s][c];
        }
    }
    __syncthreads();

    // ---- merge the two j-halves per row -> 4 candidate j's ----
    if (tid < 64) {
        unsigned long long k[4];
#pragma unroll
        for (int c = 0; c < 4; c++) k[c] = s_k[tid * 4 + c];
#pragma unroll
        for (int c = 0; c < 4; c++) top4_ins(k, s_k[(64 + tid) * 4 + c]);
#pragma unroll
        for (int c = 0; c < 4; c++) cand4[tid * 4 + c] = (int)(unsigned)k[c];
    }
    __syncthreads();

    // ---- exact fp32 refine of the 4 candidates (1 warp : 8 rows) ----
    for (int i = 0; i < 8; i++) {
        const int r = wid * 8 + i;
        const int j0c = cand4[r * 4 + 0], j1c = cand4[r * 4 + 1];
        const int j2c = cand4[r * 4 + 2], j3c = cand4[r * 4 + 3];
        const float* rv = g_resid + (size_t)(n0 + r) * Dd;
        const float* c0 = cb + (size_t)j0c * Dd;
        const float* c1 = cb + (size_t)j1c * Dd;
        const float* c2 = cb + (size_t)j2c * Dd;
        const float* c3 = cb + (size_t)j3c * Dd;
        float s0 = 0.f, s1 = 0.f, s2 = 0.f, s3 = 0.f;
#pragma unroll
        for (int kq = 0; kq < 8; kq++) {
            const float rvx = rv[kq * 32 + lane];
            s0 = fmaf(rvx, c0[kq * 32 + lane], s0);
            s1 = fmaf(rvx, c1[kq * 32 + lane], s1);
            s2 = fmaf(rvx, c2[kq * 32 + lane], s2);
            s3 = fmaf(rvx, c3[kq * 32 + lane], s3);
        }
#pragma unroll
        for (int o = 16; o; o >>= 1) {
            s0 += __shfl_down_sync(0xffffffffu, s0, o);
            s1 += __shfl_down_sync(0xffffffffu, s1, o);
            s2 += __shfl_down_sync(0xffffffffu, s2, o);
            s3 += __shfl_down_sync(0xffffffffu, s3, o);
        }
        if (!lane) {
            const float rrn = g_rr[n0 + r];
            float bd = fmaf(-2.f, s0, rrn) + ccL[j0c];
            int   bj = j0c;
            float d;
            d = fmaf(-2.f, s1, rrn) + ccL[j1c];
            if (d < bd || (d == bd && j1c < bj)) { bd = d; bj = j1c; }
            d = fmaf(-2.f, s2, rrn) + ccL[j2c];
            if (d < bd || (d == bd && j2c < bj)) { bd = d; bj = j2c; }
            d = fmaf(-2.f, s3, rrn) + ccL[j3c];
            if (d < bd || (d == bd && j3c < bj)) { bd = d; bj = j3c; }
            sidx[r] = bj;
        }
    }
    __syncthreads();

    // ---- fused update: resid -= cb[idx]; new norms; codes; loss ----
    float wl = 0.f;
    for (int m = wid; m < MTILE; m += 8) {
        const int j = sidx[m];
        const float* q = cb + (size_t)j * Dd;
        float* rout = g_resid + (size_t)(n0 + m) * Dd;
        float s = 0.f;
#pragma unroll
        for (int i = 0; i < 8; i++) {
            const int d = i * 32 + lane;
            const float rn = rout[d] - q[d];
            rout[d] = rn;
            s = fmaf(rn, rn, s);
        }
#pragma unroll
        for (int o = 16; o; o >>= 1) s += __shfl_down_sync(0xffffffffu, s, o);
        if (!lane) {
            g_rr[n0 + m] = s;
            wl += s;
            if (codes_out) codes_out[(size_t)layer * NVEC + n0 + m] = (float)j;
        }
    }
    if (!lane) wloss[wid] = wl;
    __syncthreads();
    if (tid == 0) {
        float t = 0.f;
#pragma unroll
        for (int w = 0; w < 8; w++) t += wloss[w];
        g_losspart[layer * GRID_L + blockIdx.x] = t;
    }
}

// ---------------- kernel: quantized = x - resid_final, + loss ---------------
__global__ void finalize_kernel(const float* __restrict__ x,
                                float* __restrict__ out,
                                float* __restrict__ loss_dst) {
    __shared__ float tile[32][33];
    const int b  = blockIdx.z;
    const int d0 = blockIdx.y * 32;
    const int t0 = blockIdx.x * 32;
    const int tx = threadIdx.x, ty = threadIdx.y;
#pragma unroll
    for (int i = 0; i < 32; i += 8)
        tile[ty + i][tx] = g_resid[(size_t)(b * Tt + t0 + ty + i) * Dd + d0 + tx];
    __syncthreads();
#pragma unroll
    for (int i = 0; i < 32; i += 8) {
        const size_t idx = (size_t)b * Dd * Tt + (size_t)(d0 + ty + i) * Tt + t0 + tx;
        out[idx] = x[idx] - tile[tx][ty + i];
    }
    if (loss_dst && blockIdx.x == 0 && blockIdx.y == 0 && blockIdx.z == 0 && ty == 0) {
        double s = 0.0;
        for (int i = tx; i < NQ * GRID_L; i += 32) s += (double)g_losspart[i];
#pragma unroll
        for (int o = 16; o; o >>= 1) s += __shfl_down_sync(0xffffffffu, s, o);
        if (tx == 0)
            *loss_dst = (float)(s / ((double)NQ * (double)NVEC * (double)Dd));
    }
}

// ---------------- launch -----------------------------------------------------
extern "C" void kernel_launch(void* const* d_in, const int* in_sizes, int n_in,
                              void* d_out, int out_size) {
    const float* x   = (const float*)d_in[0];
    const float* cbs = (const float*)d_in[1];
    float* out = (float*)d_out;

    const long long QN = (long long)Bb * Dd * Tt;
    const long long CN = (long long)NQ * Bb * Tt;
    float* codes = ((long long)out_size >= QN + CN) ? out + QN : nullptr;
    float* lossp = ((long long)out_size >= QN + CN + 1) ? out + QN + CN : nullptr;

    cudaFuncSetAttribute(rvq_layer_kernel,
                         cudaFuncAttributeMaxDynamicSharedMemorySize,
                         SMEM_BYTES_L);

    transpose_in_kernel<<<dim3(Tt / 32, Dd / 32, Bb), dim3(32, 8)>>>(x);
    rownorm_kernel<<<NVEC / 8, 256>>>();
    codenorm_kernel<<<NQ * NBINS / 8, 256>>>(cbs);
    cbfrag_prep<<<1024, 256>>>(cbs);
    for (int l = 0; l < NQ; l++) {
        rvq_layer_kernel<<<GRID_L, NTH, SMEM_BYTES_L>>>(
            cbs + (size_t)l * NBINS * Dd, l, codes);
    }
    finalize_kernel<<<dim3(Tt / 32, Dd / 32, Bb), dim3(32, 8)>>>(x, out, lossp);
}

// round 16
// speedup vs baseline: 3.7541x; 1.1543x over previous
#include <cuda_runtime.h>

// ---------------------------------------------------------------------------
// RVQ, 8 layers. R13 (resubmit after infra fail): ALL layers fused in one
//  kernel. Residual lives in smem fp32 across layers (re-packed to bf16 frags
//  per layer). bf16 m16n8k16 mma, branchless top-4 with 32-bit sortable keys,
//  exact fp32 re-rank of the 4 candidates (reference math, same reduce order
//  as prior passing rounds). MTILE=32, 2 CTAs/SM, grid 2048.
// ---------------------------------------------------------------------------

namespace {
constexpr int Bb    = 16;
constexpr int Dd    = 256;
constexpr int Tt    = 4096;
constexpr int NQ    = 8;
constexpr int NBINS = 1024;
constexpr int NVEC  = Bb * Tt;        // 65536
constexpr int MTILE = 32;
constexpr int GRID_F = NVEC / MTILE;  // 2048
constexpr int NTH   = 256;
constexpr int RS    = 264;            // resid smem row stride (floats)

constexpr int AF4U = 1024;            // A frags: 2 mb x 16 c16 x 32 lanes (uint4)
constexpr int BS4U = 1024;            // per buffer: 4 c16 x 8 p' x 32 lanes (uint4)
constexpr int SMEM_BYTES_L = (AF4U + 2 * BS4U) * 16  // 49152
                           + 32 * RS * 4             // resid fp32
                           + 128 * 4                 // ccs
                           + 512 * 4                 // s_k [4][32][4] u32
                           + 128 * 4                 // cand4 [32][4]
                           + 32 * 4                  // rr_s [32]
                           + 32 * 4;                 // wloss [8]+pad => 86272
}

// ---------------- device scratch --------------------------------------------
__device__ __align__(16) float g_resid[(size_t)NVEC * Dd];      // 64 MB
__device__ __align__(16) float g_cc[NQ * NBINS];
__device__ __align__(16) float g_losspart[GRID_F];
__device__ __align__(16) uint4 g_cbfrag[262144];                // 4 MB bf16 frags

// ---------------- helpers ----------------------------------------------------
// pack two floats to bf16x2: low 16 bits = lo (even k), high = hi (odd k)
__device__ __forceinline__ unsigned pbf2(float lo, float hi) {
    unsigned r;
    asm("cvt.rn.bf16x2.f32 %0, %1, %2;" : "=r"(r) : "f"(hi), "f"(lo));
    return r;
}
__device__ __forceinline__ void mma_bf16(float* d,
                                         unsigned a0, unsigned a1, unsigned a2, unsigned a3,
                                         unsigned b0, unsigned b1) {
    asm volatile(
        "mma.sync.aligned.m16n8k16.row.col.f32.bf16.bf16.f32 "
        "{%0,%1,%2,%3},{%4,%5,%6,%7},{%8,%9},{%0,%1,%2,%3};"
        : "+f"(d[0]), "+f"(d[1]), "+f"(d[2]), "+f"(d[3])
        : "r"(a0), "r"(a1), "r"(a2), "r"(a3), "r"(b0), "r"(b1));
}
// 32-bit order-preserving key: flip(dist) high 22 bits | j (10 bits).
__device__ __forceinline__ unsigned dkey32(float d, int j) {
    unsigned u = __float_as_uint(d);
    u ^= ((unsigned)((int)u >> 31)) | 0x80000000u;
    return (u & 0xFFFFFC00u) | (unsigned)j;
}
__device__ __forceinline__ unsigned umn(unsigned a, unsigned b) { return a < b ? a : b; }
__device__ __forceinline__ unsigned umx(unsigned a, unsigned b) { return a < b ? b : a; }
__device__ __forceinline__ void top4i(unsigned k[4], unsigned x) {
    unsigned t;
    t = umn(k[0], x); x = umx(k[0], x); k[0] = t;
    t = umn(k[1], x); x = umx(k[1], x); k[1] = t;
    t = umn(k[2], x); x = umx(k[2], x); k[2] = t;
    k[3] = umn(k[3], x);
}

// ---------------- kernel: transpose x[B,D,T] -> resid[n][d] -----------------
__global__ void transpose_in_kernel(const float* __restrict__ x) {
    __shared__ float tile[32][33];
    const int b  = blockIdx.z;
    const int d0 = blockIdx.y * 32;
    const int t0 = blockIdx.x * 32;
    const int tx = threadIdx.x, ty = threadIdx.y;
    const float* xb = x + (size_t)b * Dd * Tt;
#pragma unroll
    for (int i = 0; i < 32; i += 8)
        tile[ty + i][tx] = xb[(size_t)(d0 + ty + i) * Tt + t0 + tx];
    __syncthreads();
#pragma unroll
    for (int i = 0; i < 32; i += 8) {
        const int t = t0 + ty + i;
        g_resid[(size_t)(b * Tt + t) * Dd + d0 + tx] = tile[tx][ty + i];
    }
}

// ---------------- kernel: codebook squared norms ----------------------------
__global__ void codenorm_kernel(const float* __restrict__ cbs) {
    const int c    = blockIdx.x * 8 + (threadIdx.x >> 5);
    const int lane = threadIdx.x & 31;
    const float* r = cbs + (size_t)c * Dd;
    float s = 0.f;
#pragma unroll
    for (int i = 0; i < 8; i++) { float v = r[i * 32 + lane]; s = fmaf(v, v, s); }
#pragma unroll
    for (int o = 16; o; o >>= 1) s += __shfl_down_sync(0xffffffffu, s, o);
    if (!lane) g_cc[c] = s;
}

// ---------------- kernel: fragment-ordered bf16 codebook --------------------
// idx bits = layer(3) | jb(3) | c16(4) | p(3) | lane(5)   -> 262144
__global__ void cbfrag_prep(const float* __restrict__ cbs) {
    const unsigned idx = blockIdx.x * 256 + threadIdx.x;
    const int lane  = idx & 31;
    const int p     = (idx >> 5) & 7;
    const int c16   = (idx >> 8) & 15;
    const int jb    = (idx >> 12) & 7;
    const int layer = (int)(idx >> 15);
    uint4 o;
    unsigned* oe = &o.x;
#pragma unroll
    for (int e = 0; e < 4; e++) {
        const int nt = 2 * p + (e >> 1);
        const int r  = e & 1;
        const int j  = jb * 128 + nt * 8 + (lane >> 2);
        const int k  = c16 * 16 + r * 8 + 2 * (lane & 3);
        const float* src = cbs + ((size_t)layer * NBINS + j) * Dd + k;
        oe[e] = pbf2(src[0], src[1]);
    }
    g_cbfrag[idx] = o;
}

// ---------------- kernel: ALL RVQ layers fused --------------------------------
__global__ __launch_bounds__(NTH, 2)
void rvq_all_kernel(const float* __restrict__ cbs,    // [8][1024][256]
                    float* __restrict__ codes_out)
{
    extern __shared__ uint4 smu[];
    uint4* Af4   = smu;                               // [2 mb][16 c16][32 lane]
    uint4* Bs4   = smu + AF4U;                        // [2 buf][4 c16][8 p'][32]
    float* resid = (float*)(smu + AF4U + 2 * BS4U);   // [32][RS] fp32
    float* ccs   = resid + 32 * RS;                   // [128]
    unsigned* s_k = (unsigned*)(ccs + 128);           // [4 jq][32 row][4]
    int*   cand4 = (int*)(s_k + 512);                 // [32][4]
    float* rr_s  = (float*)(cand4 + 128);             // [32]
    float* wloss = rr_s + 32;                         // [8]

    const int tid  = threadIdx.x;
    const int wid  = tid >> 5;
    const int lane = tid & 31;
    const int mb   = wid >> 2;   // 0..1 : 16-row block
    const int jq   = wid & 3;    // 0..3 : j-quarter (32 j of 128)
    const int n0   = blockIdx.x * MTILE;

    // ---- initial residual load (global -> smem fp32) ----
    for (int i = tid; i < 32 * 64; i += NTH) {
        const int row = i >> 6, c4 = (i & 63) << 2;
        const float4 v = *(const float4*)(g_resid + (size_t)(n0 + row) * Dd + c4);
        *(float4*)(resid + row * RS + c4) = v;
    }
    __syncthreads();

    // ---- initial row norms ----
#pragma unroll
    for (int i = 0; i < 4; i++) {
        const int m = wid * 4 + i;
        float s = 0.f;
#pragma unroll
        for (int kq = 0; kq < 8; kq++) {
            const float v = resid[m * RS + kq * 32 + lane];
            s = fmaf(v, v, s);
        }
#pragma unroll
        for (int o = 16; o; o >>= 1) s += __shfl_down_sync(0xffffffffu, s, o);
        if (!lane) rr_s[m] = s;
    }

    float wl = 0.f;

#pragma unroll 1
    for (int layer = 0; layer < NQ; layer++) {
        const float* cb  = cbs + (size_t)layer * NBINS * Dd;
        const float* ccL = g_cc + layer * NBINS;
        __syncthreads();   // residual stable across warps before A-pack

        // ---- A-pack: smem fp32 resid -> bf16 fragments ----
#pragma unroll
        for (int u = 0; u < 4; u++) {
            const int pr  = wid * 4 + u;
            const int pmb = pr >> 4, c16 = pr & 15;
            const float* bp = resid + (pmb * 16 + (lane >> 2)) * RS
                             + c16 * 16 + 2 * (lane & 3);
            const float2 v0 = *(const float2*)(bp);
            const float2 v1 = *(const float2*)(bp + 8 * RS);
            const float2 v2 = *(const float2*)(bp + 8);
            const float2 v3 = *(const float2*)(bp + 8 * RS + 8);
            uint4 f;
            f.x = pbf2(v0.x, v0.y);
            f.y = pbf2(v1.x, v1.y);
            f.z = pbf2(v2.x, v2.y);
            f.w = pbf2(v3.x, v3.y);
            Af4[(pmb * 16 + c16) * 32 + lane] = f;
        }

        unsigned bk[2][4];
#pragma unroll
        for (int s = 0; s < 2; s++)
#pragma unroll
            for (int c = 0; c < 4; c++) bk[s][c] = 0xFFFFFFFFu;
        __syncthreads();

        // ---- 8 j-tiles of 128 codes ----
#pragma unroll 1
        for (int jt = 0; jt < 8; jt++) {
            const int j0 = jt * 128;
            const unsigned gbase = ((unsigned)layer * 8 + jt) * 4096u;

            float acc[4][4];
#pragma unroll
            for (int nt = 0; nt < 4; nt++)
#pragma unroll
                for (int c = 0; c < 4; c++) acc[nt][c] = 0.f;

            if (tid < 128) ccs[tid] = ccL[j0 + tid];
#pragma unroll
            for (int i = 0; i < 4; i++)
                Bs4[i * 256 + tid] = g_cbfrag[gbase + i * 256 + tid];
            __syncthreads();

#pragma unroll 1
            for (int ch = 0; ch < 4; ch++) {
                uint4 pf[4];
                if (ch < 3) {
                    const unsigned src = gbase + (unsigned)(ch + 1) * 1024u;
#pragma unroll
                    for (int i = 0; i < 4; i++) pf[i] = g_cbfrag[src + i * 256 + tid];
                }
                const uint4* bbuf = Bs4 + (ch & 1) * BS4U;
#pragma unroll
                for (int c16l = 0; c16l < 4; c16l++) {
                    const int c16 = ch * 4 + c16l;
                    const uint4 a  = Af4[(mb * 16 + c16) * 32 + lane];
                    const uint4 b0 = bbuf[(c16l * 8 + 2 * jq) * 32 + lane];
                    const uint4 b1 = bbuf[(c16l * 8 + 2 * jq + 1) * 32 + lane];
                    mma_bf16(acc[0], a.x, a.y, a.z, a.w, b0.x, b0.y);
                    mma_bf16(acc[1], a.x, a.y, a.z, a.w, b0.z, b0.w);
                    mma_bf16(acc[2], a.x, a.y, a.z, a.w, b1.x, b1.y);
                    mma_bf16(acc[3], a.x, a.y, a.z, a.w, b1.z, b1.w);
                }
                if (ch < 3) {
                    uint4* dst = Bs4 + ((ch + 1) & 1) * BS4U;
#pragma unroll
                    for (int i = 0; i < 4; i++) dst[i * 256 + tid] = pf[i];
                }
                __syncthreads();
            }

            // epilogue: approx dists (rr omitted: row-constant), top-4 keys.
#pragma unroll
            for (int p = 0; p < 4; p++) {
                const int nt = jq * 4 + p;
                const int jl = nt * 8 + 2 * (lane & 3);
                const int j  = j0 + jl;
                const float d0 = fmaf(-2.f, acc[p][0], ccs[jl]);
                const float d1 = fmaf(-2.f, acc[p][1], ccs[jl + 1]);
                const float d2 = fmaf(-2.f, acc[p][2], ccs[jl]);
                const float d3 = fmaf(-2.f, acc[p][3], ccs[jl + 1]);
                top4i(bk[0], dkey32(d0, j));
                top4i(bk[0], dkey32(d1, j + 1));
                top4i(bk[1], dkey32(d2, j));
                top4i(bk[1], dkey32(d3, j + 1));
            }
            __syncthreads();
        }

        // ---- merge top-4 across the 4 lanes sharing a row ----
#pragma unroll
        for (int s = 0; s < 2; s++) {
#pragma unroll
            for (int off = 1; off <= 2; off <<= 1) {
                unsigned ok[4];
#pragma unroll
                for (int c = 0; c < 4; c++)
                    ok[c] = __shfl_xor_sync(0xffffffffu, bk[s][c], off);
#pragma unroll
                for (int c = 0; c < 4; c++) top4i(bk[s], ok[c]);
            }
            if ((lane & 3) == 0) {
                const int r = mb * 16 + s * 8 + (lane >> 2);
#pragma unroll
                for (int c = 0; c < 4; c++)
                    s_k[(jq * 32 + r) * 4 + c] = bk[s][c];
            }
        }
        __syncthreads();

        // ---- merge 4 j-quarters per row -> 4 candidate j's ----
        if (tid < 32) {
            unsigned k[4];
#pragma unroll
            for (int c = 0; c < 4; c++) k[c] = s_k[tid * 4 + c];
#pragma unroll
            for (int q = 1; q < 4; q++)
#pragma unroll
                for (int c = 0; c < 4; c++) top4i(k, s_k[(q * 32 + tid) * 4 + c]);
#pragma unroll
            for (int c = 0; c < 4; c++) cand4[tid * 4 + c] = (int)(k[c] & 1023u);
        }
        __syncthreads();

        // ---- exact fp32 refine (warp owns rows wid*4..+3; resid from smem) --
        int jsel[4];
#pragma unroll
        for (int i = 0; i < 4; i++) {
            const int r = wid * 4 + i;
            const int j0c = cand4[r * 4 + 0], j1c = cand4[r * 4 + 1];
            const int j2c = cand4[r * 4 + 2], j3c = cand4[r * 4 + 3];
            const float* rv = resid + r * RS;
            const float* c0 = cb + (size_t)j0c * Dd;
            const float* c1 = cb + (size_t)j1c * Dd;
            const float* c2 = cb + (size_t)j2c * Dd;
            const float* c3 = cb + (size_t)j3c * Dd;
            float s0 = 0.f, s1 = 0.f, s2 = 0.f, s3 = 0.f;
#pragma unroll
            for (int kq = 0; kq < 8; kq++) {
                const float rvx = rv[kq * 32 + lane];
                s0 = fmaf(rvx, c0[kq * 32 + lane], s0);
                s1 = fmaf(rvx, c1[kq * 32 + lane], s1);
                s2 = fmaf(rvx, c2[kq * 32 + lane], s2);
                s3 = fmaf(rvx, c3[kq * 32 + lane], s3);
            }
#pragma unroll
            for (int o = 16; o; o >>= 1) {
                s0 += __shfl_down_sync(0xffffffffu, s0, o);
                s1 += __shfl_down_sync(0xffffffffu, s1, o);
                s2 += __shfl_down_sync(0xffffffffu, s2, o);
                s3 += __shfl_down_sync(0xffffffffu, s3, o);
            }
            int bj = 0;
            if (lane == 0) {
                const float rrn = rr_s[r];
                float bd = fmaf(-2.f, s0, rrn) + ccL[j0c];
                bj = j0c;
                float d;
                d = fmaf(-2.f, s1, rrn) + ccL[j1c];
                if (d < bd || (d == bd && j1c < bj)) { bd = d; bj = j1c; }
                d = fmaf(-2.f, s2, rrn) + ccL[j2c];
                if (d < bd || (d == bd && j2c < bj)) { bd = d; bj = j2c; }
                d = fmaf(-2.f, s3, rrn) + ccL[j3c];
                if (d < bd || (d == bd && j3c < bj)) { bd = d; bj = j3c; }
            }
            jsel[i] = __shfl_sync(0xffffffffu, bj, 0);
        }

        // ---- update residual in smem (warp-private rows) ----
#pragma unroll
        for (int i = 0; i < 4; i++) {
            const int m = wid * 4 + i;
            const int j = jsel[i];
            const float* q = cb + (size_t)j * Dd;
            float s = 0.f;
#pragma unroll
            for (int kq = 0; kq < 8; kq++) {
                const int d = kq * 32 + lane;
                const float rn = resid[m * RS + d] - q[d];
                resid[m * RS + d] = rn;
                s = fmaf(rn, rn, s);
            }
#pragma unroll
            for (int o = 16; o; o >>= 1) s += __shfl_down_sync(0xffffffffu, s, o);
            if (!lane) {
                rr_s[m] = s;
                wl += s;
                if (codes_out)
                    codes_out[(size_t)layer * NVEC + n0 + m] = (float)j;
            }
        }
    }

    // ---- write final residual back; per-CTA loss partial ----
    __syncthreads();
    for (int i = tid; i < 32 * 64; i += NTH) {
        const int row = i >> 6, c4 = (i & 63) << 2;
        *(float4*)(g_resid + (size_t)(n0 + row) * Dd + c4) =
            *(const float4*)(resid + row * RS + c4);
    }
    if (!lane) wloss[wid] = wl;
    __syncthreads();
    if (tid == 0) {
        float t = 0.f;
#pragma unroll
        for (int w = 0; w < 8; w++) t += wloss[w];
        g_losspart[blockIdx.x] = t;
    }
}

// ---------------- kernel: quantized = x - resid_final, + loss ---------------
__global__ void finalize_kernel(const float* __restrict__ x,
                                float* __restrict__ out,
                                float* __restrict__ loss_dst) {
    __shared__ float tile[32][33];
    const int b  = blockIdx.z;
    const int d0 = blockIdx.y * 32;
    const int t0 = blockIdx.x * 32;
    const int tx = threadIdx.x, ty = threadIdx.y;
#pragma unroll
    for (int i = 0; i < 32; i += 8)
        tile[ty + i][tx] = g_resid[(size_t)(b * Tt + t0 + ty + i) * Dd + d0 + tx];
    __syncthreads();
#pragma unroll
    for (int i = 0; i < 32; i += 8) {
        const size_t idx = (size_t)b * Dd * Tt + (size_t)(d0 + ty + i) * Tt + t0 + tx;
        out[idx] = x[idx] - tile[tx][ty + i];
    }
    if (loss_dst && blockIdx.x == 0 && blockIdx.y == 0 && blockIdx.z == 0 && ty == 0) {
        double s = 0.0;
        for (int i = tx; i < GRID_F; i += 32) s += (double)g_losspart[i];
#pragma unroll
        for (int o = 16; o; o >>= 1) s += __shfl_down_sync(0xffffffffu, s, o);
        if (tx == 0)
            *loss_dst = (float)(s / ((double)NQ * (double)NVEC * (double)Dd));
    }
}

// ---------------- launch -----------------------------------------------------
extern "C" void kernel_launch(void* const* d_in, const int* in_sizes, int n_in,
                              void* d_out, int out_size) {
    const float* x   = (const float*)d_in[0];
    const float* cbs = (const float*)d_in[1];
    float* out = (float*)d_out;

    const long long QN = (long long)Bb * Dd * Tt;
    const long long CN = (long long)NQ * Bb * Tt;
    float* codes = ((long long)out_size >= QN + CN) ? out + QN : nullptr;
    float* lossp = ((long long)out_size >= QN + CN + 1) ? out + QN + CN : nullptr;

    cudaFuncSetAttribute(rvq_all_kernel,
                         cudaFuncAttributeMaxDynamicSharedMemorySize,
                         SMEM_BYTES_L);

    transpose_in_kernel<<<dim3(Tt / 32, Dd / 32, Bb), dim3(32, 8)>>>(x);
    codenorm_kernel<<<NQ * NBINS / 8, 256>>>(cbs);
    cbfrag_prep<<<1024, 256>>>(cbs);
    rvq_all_kernel<<<GRID_F, NTH, SMEM_BYTES_L>>>(cbs, codes);
    finalize_kernel<<<dim3(Tt / 32, Dd / 32, Bb), dim3(32, 8)>>>(x, out, lossp);
}